// round 3
// baseline (speedup 1.0000x reference)
#include <cuda_runtime.h>
#include <math.h>

// Problem constants
#define SQ   1024
#define NB   4
#define DM   1024
#define NH   16
#define DH   64
#define DFFN 4096
#define NROW 4096          // S*B = pseudo (B'*S') rows
#define EPSV 1e-5f
#define SS   1048576       // S*S
#define BSS  16777216      // H*S*S (per-batch score stride)

// ---- scratch (static device globals; no allocation allowed) ----
static __device__ float g_Yq[NROW * DM];
static __device__ float g_Yk[NROW * DM];
static __device__ float g_Yv[NROW * DM];
static __device__ float g_emd[67108864];   // (B,H,S,S) 256MB
static __device__ float g_sc [67108864];   // (B,H,S,S) 256MB
static __device__ float g_lse[16777216];   // (H,S,S)    64MB
static __device__ float g_att[NROW * DM];
static __device__ float g_h1 [NROW * DM];
static __device__ float g_mid[NROW * DFFN];
static __device__ float g_ffn[NROW * DM];

// ============================================================
// Generic SGEMM: C[M,N] = A[M,K] @ B[N,K]^T (+bias)(+relu)
// BM=128, BN=64, BK=16, 256 threads, 8x4 per thread
// ============================================================
template<int DO_BIAS, int DO_RELU>
__global__ __launch_bounds__(256)
void sgemm_abt(const float* __restrict__ A, const float* __restrict__ B,
               const float* __restrict__ bias, float* __restrict__ C,
               int M, int N, int K) {
    __shared__ __align__(16) float As[16][128];
    __shared__ __align__(16) float Bs[16][64];
    const int tid = threadIdx.x;
    const int tx = tid & 15, ty = tid >> 4;
    const int m0 = blockIdx.y * 128, n0 = blockIdx.x * 64;
    const int lm = tid >> 1, lk = (tid & 1) * 8;   // A loader
    const int bn = tid >> 2, bk = (tid & 3) * 4;   // B loader

    float acc[8][4];
#pragma unroll
    for (int i = 0; i < 8; i++)
#pragma unroll
        for (int j = 0; j < 4; j++) acc[i][j] = 0.f;

    const float* Ap = A + (size_t)(m0 + lm) * K + lk;
    const float* Bp = B + (size_t)(n0 + bn) * K + bk;

    for (int k0 = 0; k0 < K; k0 += 16) {
        float4 a0 = *(const float4*)(Ap + k0);
        float4 a1 = *(const float4*)(Ap + k0 + 4);
        float4 b0 = *(const float4*)(Bp + k0);
        As[lk + 0][lm] = a0.x; As[lk + 1][lm] = a0.y;
        As[lk + 2][lm] = a0.z; As[lk + 3][lm] = a0.w;
        As[lk + 4][lm] = a1.x; As[lk + 5][lm] = a1.y;
        As[lk + 6][lm] = a1.z; As[lk + 7][lm] = a1.w;
        Bs[bk + 0][bn] = b0.x; Bs[bk + 1][bn] = b0.y;
        Bs[bk + 2][bn] = b0.z; Bs[bk + 3][bn] = b0.w;
        __syncthreads();
#pragma unroll
        for (int k = 0; k < 16; k++) {
            float4 av0 = *(const float4*)&As[k][ty * 8];
            float4 av1 = *(const float4*)&As[k][ty * 8 + 4];
            float4 bv  = *(const float4*)&Bs[k][tx * 4];
            float am[8] = {av0.x, av0.y, av0.z, av0.w, av1.x, av1.y, av1.z, av1.w};
            float bb[4] = {bv.x, bv.y, bv.z, bv.w};
#pragma unroll
            for (int i = 0; i < 8; i++)
#pragma unroll
                for (int j = 0; j < 4; j++)
                    acc[i][j] = fmaf(am[i], bb[j], acc[i][j]);
        }
        __syncthreads();
    }

    float4 bvv = make_float4(0.f, 0.f, 0.f, 0.f);
    if (DO_BIAS) bvv = *(const float4*)(bias + n0 + tx * 4);
#pragma unroll
    for (int i = 0; i < 8; i++) {
        float4 o;
        o.x = acc[i][0] + bvv.x; o.y = acc[i][1] + bvv.y;
        o.z = acc[i][2] + bvv.z; o.w = acc[i][3] + bvv.w;
        if (DO_RELU) {
            o.x = fmaxf(o.x, 0.f); o.y = fmaxf(o.y, 0.f);
            o.z = fmaxf(o.z, 0.f); o.w = fmaxf(o.w, 0.f);
        }
        *(float4*)(C + (size_t)(m0 + ty * 8 + i) * N + n0 + tx * 4) = o;
    }
}

// ============================================================
// emd[b,h,s,j] = sum_i Q[b,h,s,i] * rel_w[b,h,i,j]
// 64x64 tile, K=64 full. 256 threads, 4x4/thread.
// ============================================================
__global__ __launch_bounds__(256)
void emd_kernel(const float* __restrict__ Yq, const float* __restrict__ relw,
                float* __restrict__ emd) {
    const int bh = blockIdx.z;
    const int b = bh >> 4, h = bh & 15;
    const int s0 = blockIdx.y * 64, j0 = blockIdx.x * 64;
    __shared__ __align__(16) float Qs[64][68];   // [i][s]
    __shared__ __align__(16) float Rs[64][64];   // [i][j]
    const int tid = threadIdx.x;
    const int tx = tid & 15, ty = tid >> 4;

#pragma unroll
    for (int u = 0; u < 16; u++) {
        int idx = tid + u * 256;
        int r = idx >> 6, c = idx & 63;   // r = s (or i for Rs), c = i (or j)
        Qs[c][r] = Yq[(size_t)(b * SQ + s0 + r) * DM + h * DH + c];
        Rs[r][c] = relw[((size_t)bh * DH + r) * SQ + j0 + c];
    }
    __syncthreads();

    float acc[4][4];
#pragma unroll
    for (int i = 0; i < 4; i++)
#pragma unroll
        for (int j = 0; j < 4; j++) acc[i][j] = 0.f;

#pragma unroll 8
    for (int i = 0; i < 64; i++) {
        float4 q = *(const float4*)&Qs[i][ty * 4];
        float4 r = *(const float4*)&Rs[i][tx * 4];
        float qa[4] = {q.x, q.y, q.z, q.w};
        float ra[4] = {r.x, r.y, r.z, r.w};
#pragma unroll
        for (int a = 0; a < 4; a++)
#pragma unroll
            for (int c = 0; c < 4; c++)
                acc[a][c] = fmaf(qa[a], ra[c], acc[a][c]);
    }

#pragma unroll
    for (int a = 0; a < 4; a++) {
        float4 o = make_float4(acc[a][0], acc[a][1], acc[a][2], acc[a][3]);
        *(float4*)(emd + (size_t)bh * SS + (size_t)(s0 + ty * 4 + a) * SQ + j0 + tx * 4) = o;
    }
}

// ============================================================
// scores[b,h,s,t] = 0.125 * sum_i Q[s,i]K[t,i]  + skew bias
// skew bias = (t<=s) ? emd[b,h,s, 1023 + t - s] : 0
// ============================================================
__global__ __launch_bounds__(256)
void scores_kernel(const float* __restrict__ Yq, const float* __restrict__ Yk,
                   const float* __restrict__ emd, float* __restrict__ sc) {
    const int bh = blockIdx.z;
    const int b = bh >> 4, h = bh & 15;
    const int s0 = blockIdx.y * 64, t0 = blockIdx.x * 64;
    __shared__ __align__(16) float Qs[64][68];   // [i][s]
    __shared__ __align__(16) float Ks[64][68];   // [i][t]
    const int tid = threadIdx.x;
    const int tx = tid & 15, ty = tid >> 4;

#pragma unroll
    for (int u = 0; u < 16; u++) {
        int idx = tid + u * 256;
        int r = idx >> 6, c = idx & 63;
        Qs[c][r] = Yq[(size_t)(b * SQ + s0 + r) * DM + h * DH + c];
        Ks[c][r] = Yk[(size_t)(b * SQ + t0 + r) * DM + h * DH + c];
    }
    __syncthreads();

    float acc[4][4];
#pragma unroll
    for (int i = 0; i < 4; i++)
#pragma unroll
        for (int j = 0; j < 4; j++) acc[i][j] = 0.f;

#pragma unroll 8
    for (int i = 0; i < 64; i++) {
        float4 q = *(const float4*)&Qs[i][ty * 4];
        float4 k = *(const float4*)&Ks[i][tx * 4];
        float qa[4] = {q.x, q.y, q.z, q.w};
        float ka[4] = {k.x, k.y, k.z, k.w};
#pragma unroll
        for (int a = 0; a < 4; a++)
#pragma unroll
            for (int c = 0; c < 4; c++)
                acc[a][c] = fmaf(qa[a], ka[c], acc[a][c]);
    }

    const size_t base = (size_t)bh * SS;
#pragma unroll
    for (int a = 0; a < 4; a++) {
        int sg = s0 + ty * 4 + a;
#pragma unroll
        for (int c = 0; c < 4; c++) {
            int tg = t0 + tx * 4 + c;
            float v = 0.125f * acc[a][c];
            if (tg <= sg)
                v += emd[base + (size_t)sg * SQ + (1023 + tg - sg)];
            sc[base + (size_t)sg * SQ + tg] = v;
        }
    }
}

// ============================================================
// lse[h,s,t] = m + log(sum_b exp(sc[b,h,s,t]-m))  (softmax over B=4)
// ============================================================
__global__ void lse_kernel(const float* __restrict__ sc, float* __restrict__ lse) {
    int idx = blockIdx.x * blockDim.x + threadIdx.x;  // [0, H*S*S)
    float a = sc[idx];
    float b = sc[idx + BSS];
    float c = sc[idx + 2 * BSS];
    float d = sc[idx + 3 * BSS];
    float m = fmaxf(fmaxf(a, b), fmaxf(c, d));
    float s = expf(a - m) + expf(b - m) + expf(c - m) + expf(d - m);
    lse[idx] = m + logf(s);
}

// ============================================================
// O[b,h,s,d] = sum_t exp(sc[b,h,s,t]-lse[h,s,t]) * V[b,h,t,d]
// BM=64 s-rows, N=64 full, BK=32 t-chunk. 4x4/thread.
// ============================================================
__global__ __launch_bounds__(256)
void pv_kernel(const float* __restrict__ sc, const float* __restrict__ lse,
               const float* __restrict__ Yv, float* __restrict__ out) {
    const int bh = blockIdx.y;
    const int b = bh >> 4, h = bh & 15;
    const int s0 = blockIdx.x * 64;
    __shared__ __align__(16) float Ps[32][68];   // [t][s]
    __shared__ __align__(16) float Vs[32][64];   // [t][d]
    const int tid = threadIdx.x;
    const int tx = tid & 15, ty = tid >> 4;

    float acc[4][4];
#pragma unroll
    for (int i = 0; i < 4; i++)
#pragma unroll
        for (int j = 0; j < 4; j++) acc[i][j] = 0.f;

    const size_t scbase  = (size_t)bh * SS;
    const size_t lsebase = (size_t)h * SS;

    for (int t0 = 0; t0 < SQ; t0 += 32) {
#pragma unroll
        for (int u = 0; u < 8; u++) {
            int idx = tid + u * 256;
            int s = idx >> 5, t = idx & 31;
            size_t off = (size_t)(s0 + s) * SQ + t0 + t;
            Ps[t][s] = expf(sc[scbase + off] - lse[lsebase + off]);
        }
#pragma unroll
        for (int u = 0; u < 8; u++) {
            int idx = tid + u * 256;
            int t = idx >> 6, d = idx & 63;
            Vs[t][d] = Yv[(size_t)(b * SQ + t0 + t) * DM + h * DH + d];
        }
        __syncthreads();
#pragma unroll
        for (int t = 0; t < 32; t++) {
            float4 p = *(const float4*)&Ps[t][ty * 4];
            float4 v = *(const float4*)&Vs[t][tx * 4];
            float pa[4] = {p.x, p.y, p.z, p.w};
            float va[4] = {v.x, v.y, v.z, v.w};
#pragma unroll
            for (int a = 0; a < 4; a++)
#pragma unroll
                for (int c = 0; c < 4; c++)
                    acc[a][c] = fmaf(pa[a], va[c], acc[a][c]);
        }
        __syncthreads();
    }

#pragma unroll
    for (int a = 0; a < 4; a++) {
        float4 o = make_float4(acc[a][0], acc[a][1], acc[a][2], acc[a][3]);
        *(float4*)(out + (size_t)(bh * SQ + s0 + ty * 4 + a) * DH + tx * 4) = o;
    }
}

// ============================================================
// out[row,:] = LayerNorm(xa[row,:] + xb[row,:]) * g + b
// one block per row of 1024, 256 threads x 4 elems
// ============================================================
__device__ __forceinline__ float block_sum256(float v, float* red) {
#pragma unroll
    for (int o = 16; o > 0; o >>= 1) v += __shfl_xor_sync(0xffffffffu, v, o);
    int t = threadIdx.x;
    if ((t & 31) == 0) red[t >> 5] = v;
    __syncthreads();
    if (t == 0) {
        float s = 0.f;
#pragma unroll
        for (int i = 0; i < 8; i++) s += red[i];
        red[0] = s;
    }
    __syncthreads();
    float res = red[0];
    __syncthreads();
    return res;
}

__global__ __launch_bounds__(256)
void add_ln_kernel(const float* __restrict__ xa, const float* __restrict__ xb,
                   const float* __restrict__ g, const float* __restrict__ bb,
                   float* __restrict__ out) {
    const int row = blockIdx.x;
    const float* pa = xa + (size_t)row * DM;
    const float* pb = xb + (size_t)row * DM;
    __shared__ float red[8];
    const int t = threadIdx.x;

    float loc[4];
    float s = 0.f;
#pragma unroll
    for (int u = 0; u < 4; u++) {
        int i = t + u * 256;
        float v = pa[i] + pb[i];
        loc[u] = v;
        s += v;
    }
    float mean = block_sum256(s, red) * (1.f / 1024.f);

    float vs = 0.f;
#pragma unroll
    for (int u = 0; u < 4; u++) {
        float d = loc[u] - mean;
        vs += d * d;
    }
    float var = block_sum256(vs, red) * (1.f / 1024.f);
    float inv = rsqrtf(var + EPSV);

#pragma unroll
    for (int u = 0; u < 4; u++) {
        int i = t + u * 256;
        out[(size_t)row * DM + i] = (loc[u] - mean) * inv * g[i] + bb[i];
    }
}

// ============================================================
extern "C" void kernel_launch(void* const* d_in, const int* in_sizes, int n_in,
                              void* d_out, int out_size) {
    const float* x    = (const float*)d_in[0];
    const float* wq   = (const float*)d_in[1];
    const float* wk   = (const float*)d_in[2];
    const float* wv   = (const float*)d_in[3];
    const float* relw = (const float*)d_in[4];
    const float* ln1g = (const float*)d_in[5];
    const float* ln1b = (const float*)d_in[6];
    const float* ln2g = (const float*)d_in[7];
    const float* ln2b = (const float*)d_in[8];
    const float* w1   = (const float*)d_in[9];
    const float* b1   = (const float*)d_in[10];
    const float* w2   = (const float*)d_in[11];
    const float* b2   = (const float*)d_in[12];
    float* out = (float*)d_out;

    float *Yq, *Yk, *Yv, *emd, *sc, *lse, *att, *h1, *mid, *ffn;
    cudaGetSymbolAddress((void**)&Yq,  g_Yq);
    cudaGetSymbolAddress((void**)&Yk,  g_Yk);
    cudaGetSymbolAddress((void**)&Yv,  g_Yv);
    cudaGetSymbolAddress((void**)&emd, g_emd);
    cudaGetSymbolAddress((void**)&sc,  g_sc);
    cudaGetSymbolAddress((void**)&lse, g_lse);
    cudaGetSymbolAddress((void**)&att, g_att);
    cudaGetSymbolAddress((void**)&h1,  g_h1);
    cudaGetSymbolAddress((void**)&mid, g_mid);
    cudaGetSymbolAddress((void**)&ffn, g_ffn);

    // QKV projections: (4096,1024) @ (1024,1024)^T
    sgemm_abt<0, 0><<<dim3(DM / 64, NROW / 128), 256>>>(x, wq, nullptr, Yq, NROW, DM, DM);
    sgemm_abt<0, 0><<<dim3(DM / 64, NROW / 128), 256>>>(x, wk, nullptr, Yk, NROW, DM, DM);
    sgemm_abt<0, 0><<<dim3(DM / 64, NROW / 128), 256>>>(x, wv, nullptr, Yv, NROW, DM, DM);

    // relative-position logits
    emd_kernel<<<dim3(16, 16, 64), 256>>>(Yq, relw, emd);

    // attention scores + skew bias
    scores_kernel<<<dim3(16, 16, 64), 256>>>(Yq, Yk, emd, sc);

    // softmax-over-batch log-sum-exp
    lse_kernel<<<BSS / 256, 256>>>(sc, lse);

    // PV
    pv_kernel<<<dim3(16, 64), 256>>>(sc, lse, Yv, att);

    // residual + LN1
    add_ln_kernel<<<NROW, 256>>>(x, att, ln1g, ln1b, h1);

    // FFN
    sgemm_abt<1, 1><<<dim3(DFFN / 64, NROW / 128), 256>>>(h1, w1, b1, mid, NROW, DFFN, DM);
    sgemm_abt<1, 0><<<dim3(DM / 64, NROW / 128), 256>>>(mid, w2, b2, ffn, NROW, DM, DFFN);

    // residual + LN2 -> output
    add_ln_kernel<<<NROW, 256>>>(h1, ffn, ln2g, ln2b, out);

    (void)in_sizes; (void)n_in; (void)out_size;
}

// round 5
// speedup vs baseline: 1.9772x; 1.9772x over previous
#include <cuda_runtime.h>
#include <cuda_bf16.h>
#include <math.h>
#include <stdint.h>

// Problem constants
#define SQ   1024
#define NB   4
#define DM   1024
#define NH   16
#define DH   64
#define DFFN 4096
#define NROW 4096          // S*B rows
#define EPSV 1e-5f
#define SS   1048576       // S*S
#define BSS  16777216      // H*S*S

// ---- scratch (static device globals; no allocation allowed) ----
static __device__ float g_Yq[NROW * DM];
static __device__ float g_Yk[NROW * DM];
static __device__ float g_Yv[NROW * DM];
static __device__ float g_emd[67108864];   // (B,H,S,S)
static __device__ float g_sc [67108864];   // (B,H,S,S)
static __device__ float g_lse[16777216];   // (H,S,S)
static __device__ float g_att[NROW * DM];
static __device__ float g_h1 [NROW * DM];
static __device__ float g_mid[NROW * DFFN];
static __device__ float g_ffn[NROW * DM];

// ============================================================
// mma.sync bf16x2 split GEMM: C[M,N] = A[M,K] @ B[N,K]^T (+bias)(+relu)
// CTA tile 128x128, BK=32, 256 thr (8 warps, 2m x 4n), warp tile 64x32.
// D = Ah*Bh + Ah*Bl + Al*Bh (fp32 accumulate). Double-buffered SMEM.
// ============================================================
#define ASTRIDE 40                       // bf16 elems per smem row (80 B)
#define PART_BYTES (128 * ASTRIDE * 2)   // 10240 B per matrix part
#define STAGE_B (4 * PART_BYTES)         // Ah,Al,Bh,Bl = 40960 B
#define GSMEM (2 * STAGE_B)              // 81920 B

__device__ __forceinline__ uint32_t smem_u32(const void* p) {
    uint32_t a;
    asm("{ .reg .u64 t; cvta.to.shared.u64 t, %1; cvt.u32.u64 %0, t; }"
        : "=r"(a) : "l"(p));
    return a;
}

__device__ __forceinline__ void ldsm4(uint32_t addr, uint32_t* r) {
    asm volatile("ldmatrix.sync.aligned.m8n8.x4.shared.b16 {%0,%1,%2,%3}, [%4];"
                 : "=r"(r[0]), "=r"(r[1]), "=r"(r[2]), "=r"(r[3])
                 : "r"(addr));
}

__device__ __forceinline__ void mma16816(float* c, const uint32_t* a, const uint32_t* b) {
    asm volatile(
        "mma.sync.aligned.m16n8k16.row.col.f32.bf16.bf16.f32 "
        "{%0,%1,%2,%3},{%4,%5,%6,%7},{%8,%9},{%0,%1,%2,%3};"
        : "+f"(c[0]), "+f"(c[1]), "+f"(c[2]), "+f"(c[3])
        : "r"(a[0]), "r"(a[1]), "r"(a[2]), "r"(a[3]), "r"(b[0]), "r"(b[1]));
}

// 8 fp32 -> 4 packed bf16x2 hi + 4 lo
__device__ __forceinline__ void cvt_pack8(const float4 v0, const float4 v1,
                                          uint4* hi, uint4* lo) {
    float f[8] = {v0.x, v0.y, v0.z, v0.w, v1.x, v1.y, v1.z, v1.w};
    uint32_t h[4], l[4];
#pragma unroll
    for (int i = 0; i < 4; i++) {
        __nv_bfloat162 hb = __floats2bfloat162_rn(f[2 * i], f[2 * i + 1]);
        float r0 = f[2 * i]     - __bfloat162float(hb.x);
        float r1 = f[2 * i + 1] - __bfloat162float(hb.y);
        __nv_bfloat162 lb = __floats2bfloat162_rn(r0, r1);
        h[i] = *(uint32_t*)&hb;
        l[i] = *(uint32_t*)&lb;
    }
    *hi = make_uint4(h[0], h[1], h[2], h[3]);
    *lo = make_uint4(l[0], l[1], l[2], l[3]);
}

template<int DO_BIAS, int DO_RELU>
__global__ __launch_bounds__(256, 1)
void mma_gemm(const float* __restrict__ A, const float* __restrict__ B,
              const float* __restrict__ bias, float* __restrict__ C,
              int N, int K) {
    extern __shared__ char sm[];
    const int tid  = threadIdx.x;
    const int wid  = tid >> 5, lane = tid & 31;
    const int m0 = blockIdx.y * 128, n0 = blockIdx.x * 128;
    const int wm = (wid & 1) * 64, wn = (wid >> 1) * 32;

    float acc[4][4][4];
#pragma unroll
    for (int i = 0; i < 4; i++)
#pragma unroll
        for (int j = 0; j < 4; j++)
#pragma unroll
            for (int r = 0; r < 4; r++) acc[i][j][r] = 0.f;

    // loader mapping: thread t -> row t>>1 (0..127), k-half (t&1)*16
    const int lr = tid >> 1;
    const int lk = (tid & 1) * 16;
    const float* Ap = A + (size_t)(m0 + lr) * K + lk;
    const float* Bp = B + (size_t)(n0 + lr) * K + lk;
    const uint32_t sts_off = (uint32_t)(lr * ASTRIDE + lk) * 2;

    // LDSM base addresses (per thread)
    const uint32_t sb0 = smem_u32(sm);
    const uint32_t a_row_off = (uint32_t)((wm + (lane & 15)) * ASTRIDE) * 2
                             + ((lane >> 4) & 1) * 16;
    const uint32_t b_row_off = (uint32_t)((wn + (lane & 7) + ((lane >> 4) & 1) * 8) * ASTRIDE) * 2
                             + ((lane >> 3) & 1) * 16;

    const int NC = K >> 5;
    float4 stg[8];

    // prologue: chunk 0
#pragma unroll
    for (int i = 0; i < 4; i++) stg[i]     = *(const float4*)(Ap + i * 4);
#pragma unroll
    for (int i = 0; i < 4; i++) stg[4 + i] = *(const float4*)(Bp + i * 4);
    {
        char* st = sm;
        uint4 h0, l0, h1, l1;
        cvt_pack8(stg[0], stg[1], &h0, &l0);
        cvt_pack8(stg[2], stg[3], &h1, &l1);
        *(uint4*)(st + sts_off)                   = h0;
        *(uint4*)(st + sts_off + 16)              = h1;
        *(uint4*)(st + PART_BYTES + sts_off)      = l0;
        *(uint4*)(st + PART_BYTES + sts_off + 16) = l1;
        cvt_pack8(stg[4], stg[5], &h0, &l0);
        cvt_pack8(stg[6], stg[7], &h1, &l1);
        *(uint4*)(st + 2 * PART_BYTES + sts_off)      = h0;
        *(uint4*)(st + 2 * PART_BYTES + sts_off + 16) = h1;
        *(uint4*)(st + 3 * PART_BYTES + sts_off)      = l0;
        *(uint4*)(st + 3 * PART_BYTES + sts_off + 16) = l1;
    }
    __syncthreads();

    for (int c = 0; c < NC; c++) {
        // issue next chunk's global loads early
        if (c + 1 < NC) {
            const int kc = (c + 1) << 5;
#pragma unroll
            for (int i = 0; i < 4; i++) stg[i]     = *(const float4*)(Ap + kc + i * 4);
#pragma unroll
            for (int i = 0; i < 4; i++) stg[4 + i] = *(const float4*)(Bp + kc + i * 4);
        }

        // compute on stage c&1
        {
            const uint32_t sbase = sb0 + (uint32_t)(c & 1) * STAGE_B;
            const uint32_t aA = sbase + a_row_off;
            const uint32_t aB = sbase + 2 * PART_BYTES + b_row_off;
#pragma unroll
            for (int ks = 0; ks < 2; ks++) {
                uint32_t Ah[4][4], Al[4][4], Bh[4][2], Bl[4][2];
#pragma unroll
                for (int mt = 0; mt < 4; mt++)
                    ldsm4(aA + mt * 1280 + ks * 32, Ah[mt]);
#pragma unroll
                for (int mt = 0; mt < 4; mt++)
                    ldsm4(aA + PART_BYTES + mt * 1280 + ks * 32, Al[mt]);
#pragma unroll
                for (int bt = 0; bt < 2; bt++) {
                    uint32_t r[4];
                    ldsm4(aB + bt * 1280 + ks * 32, r);
                    Bh[2 * bt][0] = r[0]; Bh[2 * bt][1] = r[1];
                    Bh[2 * bt + 1][0] = r[2]; Bh[2 * bt + 1][1] = r[3];
                }
#pragma unroll
                for (int bt = 0; bt < 2; bt++) {
                    uint32_t r[4];
                    ldsm4(aB + PART_BYTES + bt * 1280 + ks * 32, r);
                    Bl[2 * bt][0] = r[0]; Bl[2 * bt][1] = r[1];
                    Bl[2 * bt + 1][0] = r[2]; Bl[2 * bt + 1][1] = r[3];
                }
#pragma unroll
                for (int mt = 0; mt < 4; mt++)
#pragma unroll
                    for (int nt = 0; nt < 4; nt++)
                        mma16816(acc[mt][nt], Ah[mt], Bh[nt]);
#pragma unroll
                for (int mt = 0; mt < 4; mt++)
#pragma unroll
                    for (int nt = 0; nt < 4; nt++)
                        mma16816(acc[mt][nt], Ah[mt], Bl[nt]);
#pragma unroll
                for (int mt = 0; mt < 4; mt++)
#pragma unroll
                    for (int nt = 0; nt < 4; nt++)
                        mma16816(acc[mt][nt], Al[mt], Bh[nt]);
            }
        }

        // convert + store next chunk
        if (c + 1 < NC) {
            char* st = sm + ((c + 1) & 1) * STAGE_B;
            uint4 h0, l0, h1, l1;
            cvt_pack8(stg[0], stg[1], &h0, &l0);
            cvt_pack8(stg[2], stg[3], &h1, &l1);
            *(uint4*)(st + sts_off)                   = h0;
            *(uint4*)(st + sts_off + 16)              = h1;
            *(uint4*)(st + PART_BYTES + sts_off)      = l0;
            *(uint4*)(st + PART_BYTES + sts_off + 16) = l1;
            cvt_pack8(stg[4], stg[5], &h0, &l0);
            cvt_pack8(stg[6], stg[7], &h1, &l1);
            *(uint4*)(st + 2 * PART_BYTES + sts_off)      = h0;
            *(uint4*)(st + 2 * PART_BYTES + sts_off + 16) = h1;
            *(uint4*)(st + 3 * PART_BYTES + sts_off)      = l0;
            *(uint4*)(st + 3 * PART_BYTES + sts_off + 16) = l1;
        }
        __syncthreads();
    }

    // epilogue
    const int er = lane >> 2, ec = (lane & 3) * 2;
#pragma unroll
    for (int mt = 0; mt < 4; mt++) {
        const int row0 = m0 + wm + mt * 16 + er;
#pragma unroll
        for (int nt = 0; nt < 4; nt++) {
            const int col = n0 + wn + nt * 8 + ec;
            float2 bv = make_float2(0.f, 0.f);
            if (DO_BIAS) bv = *(const float2*)(bias + col);
            float2 o0, o1;
            o0.x = acc[mt][nt][0] + bv.x; o0.y = acc[mt][nt][1] + bv.y;
            o1.x = acc[mt][nt][2] + bv.x; o1.y = acc[mt][nt][3] + bv.y;
            if (DO_RELU) {
                o0.x = fmaxf(o0.x, 0.f); o0.y = fmaxf(o0.y, 0.f);
                o1.x = fmaxf(o1.x, 0.f); o1.y = fmaxf(o1.y, 0.f);
            }
            *(float2*)(C + (size_t)row0 * N + col)       = o0;
            *(float2*)(C + (size_t)(row0 + 8) * N + col) = o1;
        }
    }
}

// ============================================================
// emd[b,h,s,j] = sum_i Q[b,h,s,i] * rel_w[b,h,i,j]
// Only j >= 1023 - s is ever consumed by the skew — skip dead tiles.
// ============================================================
__global__ __launch_bounds__(256)
void emd_kernel(const float* __restrict__ Yq, const float* __restrict__ relw,
                float* __restrict__ emd) {
    const int bh = blockIdx.z;
    const int b = bh >> 4, h = bh & 15;
    const int s0 = blockIdx.y * 64, j0 = blockIdx.x * 64;
    if (s0 + j0 + 126 < 1023) return;   // tile never read by skew
    __shared__ __align__(16) float Qs[64][68];
    __shared__ __align__(16) float Rs[64][64];
    const int tid = threadIdx.x;
    const int tx = tid & 15, ty = tid >> 4;

#pragma unroll
    for (int u = 0; u < 16; u++) {
        int idx = tid + u * 256;
        int r = idx >> 6, c = idx & 63;
        Qs[c][r] = Yq[(size_t)(b * SQ + s0 + r) * DM + h * DH + c];
        Rs[r][c] = relw[((size_t)bh * DH + r) * SQ + j0 + c];
    }
    __syncthreads();

    float acc[4][4];
#pragma unroll
    for (int i = 0; i < 4; i++)
#pragma unroll
        for (int j = 0; j < 4; j++) acc[i][j] = 0.f;

#pragma unroll 8
    for (int i = 0; i < 64; i++) {
        float4 q = *(const float4*)&Qs[i][ty * 4];
        float4 r = *(const float4*)&Rs[i][tx * 4];
        float qa[4] = {q.x, q.y, q.z, q.w};
        float ra[4] = {r.x, r.y, r.z, r.w};
#pragma unroll
        for (int a = 0; a < 4; a++)
#pragma unroll
            for (int c = 0; c < 4; c++)
                acc[a][c] = fmaf(qa[a], ra[c], acc[a][c]);
    }

#pragma unroll
    for (int a = 0; a < 4; a++) {
        float4 o = make_float4(acc[a][0], acc[a][1], acc[a][2], acc[a][3]);
        *(float4*)(emd + (size_t)bh * SS + (size_t)(s0 + ty * 4 + a) * SQ + j0 + tx * 4) = o;
    }
}

// ============================================================
// scores[b,h,s,t] = 0.125*QK^T + skew bias
// ============================================================
__global__ __launch_bounds__(256)
void scores_kernel(const float* __restrict__ Yq, const float* __restrict__ Yk,
                   const float* __restrict__ emd, float* __restrict__ sc) {
    const int bh = blockIdx.z;
    const int b = bh >> 4, h = bh & 15;
    const int s0 = blockIdx.y * 64, t0 = blockIdx.x * 64;
    __shared__ __align__(16) float Qs[64][68];
    __shared__ __align__(16) float Ks[64][68];
    const int tid = threadIdx.x;
    const int tx = tid & 15, ty = tid >> 4;

#pragma unroll
    for (int u = 0; u < 16; u++) {
        int idx = tid + u * 256;
        int r = idx >> 6, c = idx & 63;
        Qs[c][r] = Yq[(size_t)(b * SQ + s0 + r) * DM + h * DH + c];
        Ks[c][r] = Yk[(size_t)(b * SQ + t0 + r) * DM + h * DH + c];
    }
    __syncthreads();

    float acc[4][4];
#pragma unroll
    for (int i = 0; i < 4; i++)
#pragma unroll
        for (int j = 0; j < 4; j++) acc[i][j] = 0.f;

#pragma unroll 8
    for (int i = 0; i < 64; i++) {
        float4 q = *(const float4*)&Qs[i][ty * 4];
        float4 k = *(const float4*)&Ks[i][tx * 4];
        float qa[4] = {q.x, q.y, q.z, q.w};
        float ka[4] = {k.x, k.y, k.z, k.w};
#pragma unroll
        for (int a = 0; a < 4; a++)
#pragma unroll
            for (int c = 0; c < 4; c++)
                acc[a][c] = fmaf(qa[a], ka[c], acc[a][c]);
    }

    const size_t base = (size_t)bh * SS;
#pragma unroll
    for (int a = 0; a < 4; a++) {
        int sg = s0 + ty * 4 + a;
#pragma unroll
        for (int c = 0; c < 4; c++) {
            int tg = t0 + tx * 4 + c;
            float v = 0.125f * acc[a][c];
            if (tg <= sg)
                v += emd[base + (size_t)sg * SQ + (1023 + tg - sg)];
            sc[base + (size_t)sg * SQ + tg] = v;
        }
    }
}

// ============================================================
// lse over batch dim (B=4)
// ============================================================
__global__ void lse_kernel(const float* __restrict__ sc, float* __restrict__ lse) {
    int idx = blockIdx.x * blockDim.x + threadIdx.x;
    float a = sc[idx];
    float b = sc[idx + BSS];
    float c = sc[idx + 2 * BSS];
    float d = sc[idx + 3 * BSS];
    float m = fmaxf(fmaxf(a, b), fmaxf(c, d));
    float s = expf(a - m) + expf(b - m) + expf(c - m) + expf(d - m);
    lse[idx] = m + logf(s);
}

// ============================================================
// PV
// ============================================================
__global__ __launch_bounds__(256)
void pv_kernel(const float* __restrict__ sc, const float* __restrict__ lse,
               const float* __restrict__ Yv, float* __restrict__ out) {
    const int bh = blockIdx.y;
    const int b = bh >> 4, h = bh & 15;
    const int s0 = blockIdx.x * 64;
    __shared__ __align__(16) float Ps[32][68];
    __shared__ __align__(16) float Vs[32][64];
    const int tid = threadIdx.x;
    const int tx = tid & 15, ty = tid >> 4;

    float acc[4][4];
#pragma unroll
    for (int i = 0; i < 4; i++)
#pragma unroll
        for (int j = 0; j < 4; j++) acc[i][j] = 0.f;

    const size_t scbase  = (size_t)bh * SS;
    const size_t lsebase = (size_t)h * SS;

    for (int t0 = 0; t0 < SQ; t0 += 32) {
#pragma unroll
        for (int u = 0; u < 8; u++) {
            int idx = tid + u * 256;
            int s = idx >> 5, t = idx & 31;
            size_t off = (size_t)(s0 + s) * SQ + t0 + t;
            Ps[t][s] = expf(sc[scbase + off] - lse[lsebase + off]);
        }
#pragma unroll
        for (int u = 0; u < 8; u++) {
            int idx = tid + u * 256;
            int t = idx >> 6, d = idx & 63;
            Vs[t][d] = Yv[(size_t)(b * SQ + t0 + t) * DM + h * DH + d];
        }
        __syncthreads();
#pragma unroll
        for (int t = 0; t < 32; t++) {
            float4 p = *(const float4*)&Ps[t][ty * 4];
            float4 v = *(const float4*)&Vs[t][tx * 4];
            float pa[4] = {p.x, p.y, p.z, p.w};
            float va[4] = {v.x, v.y, v.z, v.w};
#pragma unroll
            for (int a = 0; a < 4; a++)
#pragma unroll
                for (int c = 0; c < 4; c++)
                    acc[a][c] = fmaf(pa[a], va[c], acc[a][c]);
        }
        __syncthreads();
    }

#pragma unroll
    for (int a = 0; a < 4; a++) {
        float4 o = make_float4(acc[a][0], acc[a][1], acc[a][2], acc[a][3]);
        *(float4*)(out + (size_t)(bh * SQ + s0 + ty * 4 + a) * DH + tx * 4) = o;
    }
}

// ============================================================
// residual + LayerNorm
// ============================================================
__device__ __forceinline__ float block_sum256(float v, float* red) {
#pragma unroll
    for (int o = 16; o > 0; o >>= 1) v += __shfl_xor_sync(0xffffffffu, v, o);
    int t = threadIdx.x;
    if ((t & 31) == 0) red[t >> 5] = v;
    __syncthreads();
    if (t == 0) {
        float s = 0.f;
#pragma unroll
        for (int i = 0; i < 8; i++) s += red[i];
        red[0] = s;
    }
    __syncthreads();
    float res = red[0];
    __syncthreads();
    return res;
}

__global__ __launch_bounds__(256)
void add_ln_kernel(const float* __restrict__ xa, const float* __restrict__ xb,
                   const float* __restrict__ g, const float* __restrict__ bb,
                   float* __restrict__ out) {
    const int row = blockIdx.x;
    const float* pa = xa + (size_t)row * DM;
    const float* pb = xb + (size_t)row * DM;
    __shared__ float red[8];
    const int t = threadIdx.x;

    float loc[4];
    float s = 0.f;
#pragma unroll
    for (int u = 0; u < 4; u++) {
        int i = t + u * 256;
        float v = pa[i] + pb[i];
        loc[u] = v;
        s += v;
    }
    float mean = block_sum256(s, red) * (1.f / 1024.f);

    float vs = 0.f;
#pragma unroll
    for (int u = 0; u < 4; u++) {
        float d = loc[u] - mean;
        vs += d * d;
    }
    float var = block_sum256(vs, red) * (1.f / 1024.f);
    float inv = rsqrtf(var + EPSV);

#pragma unroll
    for (int u = 0; u < 4; u++) {
        int i = t + u * 256;
        out[(size_t)row * DM + i] = (loc[u] - mean) * inv * g[i] + bb[i];
    }
}

// ============================================================
extern "C" void kernel_launch(void* const* d_in, const int* in_sizes, int n_in,
                              void* d_out, int out_size) {
    const float* x    = (const float*)d_in[0];
    const float* wq   = (const float*)d_in[1];
    const float* wk   = (const float*)d_in[2];
    const float* wv   = (const float*)d_in[3];
    const float* relw = (const float*)d_in[4];
    const float* ln1g = (const float*)d_in[5];
    const float* ln1b = (const float*)d_in[6];
    const float* ln2g = (const float*)d_in[7];
    const float* ln2b = (const float*)d_in[8];
    const float* w1   = (const float*)d_in[9];
    const float* b1   = (const float*)d_in[10];
    const float* w2   = (const float*)d_in[11];
    const float* b2   = (const float*)d_in[12];
    float* out = (float*)d_out;

    float *Yq, *Yk, *Yv, *emd, *sc, *lse, *att, *h1, *mid, *ffn;
    cudaGetSymbolAddress((void**)&Yq,  g_Yq);
    cudaGetSymbolAddress((void**)&Yk,  g_Yk);
    cudaGetSymbolAddress((void**)&Yv,  g_Yv);
    cudaGetSymbolAddress((void**)&emd, g_emd);
    cudaGetSymbolAddress((void**)&sc,  g_sc);
    cudaGetSymbolAddress((void**)&lse, g_lse);
    cudaGetSymbolAddress((void**)&att, g_att);
    cudaGetSymbolAddress((void**)&h1,  g_h1);
    cudaGetSymbolAddress((void**)&mid, g_mid);
    cudaGetSymbolAddress((void**)&ffn, g_ffn);

    cudaFuncSetAttribute(mma_gemm<0, 0>, cudaFuncAttributeMaxDynamicSharedMemorySize, GSMEM);
    cudaFuncSetAttribute(mma_gemm<1, 1>, cudaFuncAttributeMaxDynamicSharedMemorySize, GSMEM);
    cudaFuncSetAttribute(mma_gemm<1, 0>, cudaFuncAttributeMaxDynamicSharedMemorySize, GSMEM);

    // QKV projections: (4096,1024) @ (1024,1024)^T — HMMA bf16x2
    mma_gemm<0, 0><<<dim3(DM / 128, NROW / 128), 256, GSMEM>>>(x, wq, nullptr, Yq, DM, DM);
    mma_gemm<0, 0><<<dim3(DM / 128, NROW / 128), 256, GSMEM>>>(x, wk, nullptr, Yk, DM, DM);
    mma_gemm<0, 0><<<dim3(DM / 128, NROW / 128), 256, GSMEM>>>(x, wv, nullptr, Yv, DM, DM);

    // relative-position logits (upper-band tiles only)
    emd_kernel<<<dim3(16, 16, 64), 256>>>(Yq, relw, emd);

    // attention scores + skew bias
    scores_kernel<<<dim3(16, 16, 64), 256>>>(Yq, Yk, emd, sc);

    // softmax-over-batch log-sum-exp
    lse_kernel<<<BSS / 256, 256>>>(sc, lse);

    // PV
    pv_kernel<<<dim3(16, 64), 256>>>(sc, lse, Yv, att);

    // residual + LN1
    add_ln_kernel<<<NROW, 256>>>(x, att, ln1g, ln1b, h1);

    // FFN — HMMA bf16x2
    mma_gemm<1, 1><<<dim3(DFFN / 128, NROW / 128), 256, GSMEM>>>(h1, w1, b1, mid, DFFN, DM);
    mma_gemm<1, 0><<<dim3(DM / 128, NROW / 128), 256, GSMEM>>>(mid, w2, b2, ffn, DM, DFFN);

    // residual + LN2 -> output
    add_ln_kernel<<<NROW, 256>>>(h1, ffn, ln2g, ln2b, out);

    (void)in_sizes; (void)n_in; (void)out_size;
}

// round 8
// speedup vs baseline: 2.1393x; 1.0820x over previous
#include <cuda_runtime.h>
#include <cuda_bf16.h>
#include <math.h>
#include <stdint.h>

// Problem constants
#define SQ   1024
#define NB   4
#define DM   1024
#define NH   16
#define DH   64
#define DFFN 4096
#define NROW 4096          // S*B rows
#define EPSV 1e-5f
#define SS   1048576       // S*S
#define BSS  16777216      // H*S*S

// ---- scratch (static device globals; no allocation allowed) ----
static __device__ float g_Yq[NROW * DM];
static __device__ float g_Yk[NROW * DM];
static __device__ float g_Yv[NROW * DM];
static __device__ float g_emd[67108864];   // (B,H,S,S)
static __device__ float g_sc [67108864];   // (B,H,S,S)
static __device__ float g_att[NROW * DM];
static __device__ float g_h1 [NROW * DM];
static __device__ float g_mid[NROW * DFFN];
static __device__ float g_ffn[NROW * DM];

// ============================================================
// common helpers
// ============================================================
__device__ __forceinline__ uint32_t smem_u32(const void* p) {
    uint32_t a;
    asm("{ .reg .u64 t; cvta.to.shared.u64 t, %1; cvt.u32.u64 %0, t; }"
        : "=r"(a) : "l"(p));
    return a;
}

__device__ __forceinline__ void ldsm4(uint32_t addr, uint32_t* r) {
    asm volatile("ldmatrix.sync.aligned.m8n8.x4.shared.b16 {%0,%1,%2,%3}, [%4];"
                 : "=r"(r[0]), "=r"(r[1]), "=r"(r[2]), "=r"(r[3])
                 : "r"(addr));
}

__device__ __forceinline__ void mma16816(float* c, const uint32_t* a, const uint32_t* b) {
    asm volatile(
        "mma.sync.aligned.m16n8k16.row.col.f32.bf16.bf16.f32 "
        "{%0,%1,%2,%3},{%4,%5,%6,%7},{%8,%9},{%0,%1,%2,%3};"
        : "+f"(c[0]), "+f"(c[1]), "+f"(c[2]), "+f"(c[3])
        : "r"(a[0]), "r"(a[1]), "r"(a[2]), "r"(a[3]), "r"(b[0]), "r"(b[1]));
}

// 8 fp32 -> 4 packed bf16x2 hi + 4 lo
__device__ __forceinline__ void cvt_pack8(const float4 v0, const float4 v1,
                                          uint4* hi, uint4* lo) {
    float f[8] = {v0.x, v0.y, v0.z, v0.w, v1.x, v1.y, v1.z, v1.w};
    uint32_t h[4], l[4];
#pragma unroll
    for (int i = 0; i < 4; i++) {
        __nv_bfloat162 hb = __floats2bfloat162_rn(f[2 * i], f[2 * i + 1]);
        float r0 = f[2 * i]     - __bfloat162float(hb.x);
        float r1 = f[2 * i + 1] - __bfloat162float(hb.y);
        __nv_bfloat162 lb = __floats2bfloat162_rn(r0, r1);
        h[i] = *(uint32_t*)&hb;
        l[i] = *(uint32_t*)&lb;
    }
    *hi = make_uint4(h[0], h[1], h[2], h[3]);
    *lo = make_uint4(l[0], l[1], l[2], l[3]);
}

// ============================================================
// mma.sync bf16x2 split GEMM: C[M,N] = A[M,K] @ B[N,K]^T (+bias)(+relu)
// CTA tile 128x128, BK=32, 256 thr (8 warps, 2m x 4n), warp tile 64x32.
// ============================================================
#define ASTRIDE 40
#define PART_BYTES (128 * ASTRIDE * 2)
#define STAGE_B (4 * PART_BYTES)
#define GSMEM (2 * STAGE_B)

template<int DO_BIAS, int DO_RELU>
__global__ __launch_bounds__(256, 1)
void mma_gemm(const float* __restrict__ A, const float* __restrict__ B,
              const float* __restrict__ bias, float* __restrict__ C,
              int N, int K) {
    extern __shared__ char sm[];
    const int tid  = threadIdx.x;
    const int wid  = tid >> 5, lane = tid & 31;
    const int m0 = blockIdx.y * 128, n0 = blockIdx.x * 128;
    const int wm = (wid & 1) * 64, wn = (wid >> 1) * 32;

    float acc[4][4][4];
#pragma unroll
    for (int i = 0; i < 4; i++)
#pragma unroll
        for (int j = 0; j < 4; j++)
#pragma unroll
            for (int r = 0; r < 4; r++) acc[i][j][r] = 0.f;

    const int lr = tid >> 1;
    const int lk = (tid & 1) * 16;
    const float* Ap = A + (size_t)(m0 + lr) * K + lk;
    const float* Bp = B + (size_t)(n0 + lr) * K + lk;
    const uint32_t sts_off = (uint32_t)(lr * ASTRIDE + lk) * 2;

    const uint32_t sb0 = smem_u32(sm);
    const uint32_t a_row_off = (uint32_t)((wm + (lane & 15)) * ASTRIDE) * 2
                             + ((lane >> 4) & 1) * 16;
    const uint32_t b_row_off = (uint32_t)((wn + (lane & 7) + ((lane >> 4) & 1) * 8) * ASTRIDE) * 2
                             + ((lane >> 3) & 1) * 16;

    const int NC = K >> 5;
    float4 stg[8];

#pragma unroll
    for (int i = 0; i < 4; i++) stg[i]     = *(const float4*)(Ap + i * 4);
#pragma unroll
    for (int i = 0; i < 4; i++) stg[4 + i] = *(const float4*)(Bp + i * 4);
    {
        char* st = sm;
        uint4 h0, l0, h1, l1;
        cvt_pack8(stg[0], stg[1], &h0, &l0);
        cvt_pack8(stg[2], stg[3], &h1, &l1);
        *(uint4*)(st + sts_off)                   = h0;
        *(uint4*)(st + sts_off + 16)              = h1;
        *(uint4*)(st + PART_BYTES + sts_off)      = l0;
        *(uint4*)(st + PART_BYTES + sts_off + 16) = l1;
        cvt_pack8(stg[4], stg[5], &h0, &l0);
        cvt_pack8(stg[6], stg[7], &h1, &l1);
        *(uint4*)(st + 2 * PART_BYTES + sts_off)      = h0;
        *(uint4*)(st + 2 * PART_BYTES + sts_off + 16) = h1;
        *(uint4*)(st + 3 * PART_BYTES + sts_off)      = l0;
        *(uint4*)(st + 3 * PART_BYTES + sts_off + 16) = l1;
    }
    __syncthreads();

    for (int c = 0; c < NC; c++) {
        if (c + 1 < NC) {
            const int kc = (c + 1) << 5;
#pragma unroll
            for (int i = 0; i < 4; i++) stg[i]     = *(const float4*)(Ap + kc + i * 4);
#pragma unroll
            for (int i = 0; i < 4; i++) stg[4 + i] = *(const float4*)(Bp + kc + i * 4);
        }
        {
            const uint32_t sbase = sb0 + (uint32_t)(c & 1) * STAGE_B;
            const uint32_t aA = sbase + a_row_off;
            const uint32_t aB = sbase + 2 * PART_BYTES + b_row_off;
#pragma unroll
            for (int ks = 0; ks < 2; ks++) {
                uint32_t Ah[4][4], Al[4][4], Bh[4][2], Bl[4][2];
#pragma unroll
                for (int mt = 0; mt < 4; mt++)
                    ldsm4(aA + mt * 1280 + ks * 32, Ah[mt]);
#pragma unroll
                for (int mt = 0; mt < 4; mt++)
                    ldsm4(aA + PART_BYTES + mt * 1280 + ks * 32, Al[mt]);
#pragma unroll
                for (int bt = 0; bt < 2; bt++) {
                    uint32_t r[4];
                    ldsm4(aB + bt * 1280 + ks * 32, r);
                    Bh[2 * bt][0] = r[0]; Bh[2 * bt][1] = r[1];
                    Bh[2 * bt + 1][0] = r[2]; Bh[2 * bt + 1][1] = r[3];
                }
#pragma unroll
                for (int bt = 0; bt < 2; bt++) {
                    uint32_t r[4];
                    ldsm4(aB + PART_BYTES + bt * 1280 + ks * 32, r);
                    Bl[2 * bt][0] = r[0]; Bl[2 * bt][1] = r[1];
                    Bl[2 * bt + 1][0] = r[2]; Bl[2 * bt + 1][1] = r[3];
                }
#pragma unroll
                for (int mt = 0; mt < 4; mt++)
#pragma unroll
                    for (int nt = 0; nt < 4; nt++)
                        mma16816(acc[mt][nt], Ah[mt], Bh[nt]);
#pragma unroll
                for (int mt = 0; mt < 4; mt++)
#pragma unroll
                    for (int nt = 0; nt < 4; nt++)
                        mma16816(acc[mt][nt], Ah[mt], Bl[nt]);
#pragma unroll
                for (int mt = 0; mt < 4; mt++)
#pragma unroll
                    for (int nt = 0; nt < 4; nt++)
                        mma16816(acc[mt][nt], Al[mt], Bh[nt]);
            }
        }
        if (c + 1 < NC) {
            char* st = sm + ((c + 1) & 1) * STAGE_B;
            uint4 h0, l0, h1, l1;
            cvt_pack8(stg[0], stg[1], &h0, &l0);
            cvt_pack8(stg[2], stg[3], &h1, &l1);
            *(uint4*)(st + sts_off)                   = h0;
            *(uint4*)(st + sts_off + 16)              = h1;
            *(uint4*)(st + PART_BYTES + sts_off)      = l0;
            *(uint4*)(st + PART_BYTES + sts_off + 16) = l1;
            cvt_pack8(stg[4], stg[5], &h0, &l0);
            cvt_pack8(stg[6], stg[7], &h1, &l1);
            *(uint4*)(st + 2 * PART_BYTES + sts_off)      = h0;
            *(uint4*)(st + 2 * PART_BYTES + sts_off + 16) = h1;
            *(uint4*)(st + 3 * PART_BYTES + sts_off)      = l0;
            *(uint4*)(st + 3 * PART_BYTES + sts_off + 16) = l1;
        }
        __syncthreads();
    }

    const int er = lane >> 2, ec = (lane & 3) * 2;
#pragma unroll
    for (int mt = 0; mt < 4; mt++) {
        const int row0 = m0 + wm + mt * 16 + er;
#pragma unroll
        for (int nt = 0; nt < 4; nt++) {
            const int col = n0 + wn + nt * 8 + ec;
            float2 bv = make_float2(0.f, 0.f);
            if (DO_BIAS) bv = *(const float2*)(bias + col);
            float2 o0, o1;
            o0.x = acc[mt][nt][0] + bv.x; o0.y = acc[mt][nt][1] + bv.y;
            o1.x = acc[mt][nt][2] + bv.x; o1.y = acc[mt][nt][3] + bv.y;
            if (DO_RELU) {
                o0.x = fmaxf(o0.x, 0.f); o0.y = fmaxf(o0.y, 0.f);
                o1.x = fmaxf(o1.x, 0.f); o1.y = fmaxf(o1.y, 0.f);
            }
            *(float2*)(C + (size_t)row0 * N + col)       = o0;
            *(float2*)(C + (size_t)(row0 + 8) * N + col) = o1;
        }
    }
}

// ============================================================
// emd[b,h,s,j] = sum_i Q[b,h,s,i] * rel_w[b,h,i,j]  (live band only)
// ============================================================
__global__ __launch_bounds__(256)
void emd_kernel(const float* __restrict__ Yq, const float* __restrict__ relw,
                float* __restrict__ emd) {
    const int bh = blockIdx.z;
    const int b = bh >> 4, h = bh & 15;
    const int s0 = blockIdx.y * 64, j0 = blockIdx.x * 64;
    if (s0 + j0 + 126 < 1023) return;
    __shared__ __align__(16) float Qs[64][68];
    __shared__ __align__(16) float Rs[64][64];
    const int tid = threadIdx.x;
    const int tx = tid & 15, ty = tid >> 4;

#pragma unroll
    for (int u = 0; u < 16; u++) {
        int idx = tid + u * 256;
        int r = idx >> 6, c = idx & 63;
        Qs[c][r] = Yq[(size_t)(b * SQ + s0 + r) * DM + h * DH + c];
        Rs[r][c] = relw[((size_t)bh * DH + r) * SQ + j0 + c];
    }
    __syncthreads();

    float acc[4][4];
#pragma unroll
    for (int i = 0; i < 4; i++)
#pragma unroll
        for (int j = 0; j < 4; j++) acc[i][j] = 0.f;

#pragma unroll 8
    for (int i = 0; i < 64; i++) {
        float4 q = *(const float4*)&Qs[i][ty * 4];
        float4 r = *(const float4*)&Rs[i][tx * 4];
        float qa[4] = {q.x, q.y, q.z, q.w};
        float ra[4] = {r.x, r.y, r.z, r.w};
#pragma unroll
        for (int a = 0; a < 4; a++)
#pragma unroll
            for (int c = 0; c < 4; c++)
                acc[a][c] = fmaf(qa[a], ra[c], acc[a][c]);
    }

#pragma unroll
    for (int a = 0; a < 4; a++) {
        float4 o = make_float4(acc[a][0], acc[a][1], acc[a][2], acc[a][3]);
        *(float4*)(emd + (size_t)bh * SS + (size_t)(s0 + ty * 4 + a) * SQ + j0 + tx * 4) = o;
    }
}

// ============================================================
// scores (HMMA): sc[b,h,s,t] = 0.125 * Q·K^T + skew band
// CTA tile 128x128 (s x t), K=64. 8 warps (2m x 4n), warp 64x32.
// ============================================================
#define SC_STRIDE 72                     // bf16 elems per row (144 B)
#define SC_PART (128 * SC_STRIDE * 2)    // 18432 B
#define SC_SMEM (4 * SC_PART)            // 73728 B

__global__ __launch_bounds__(256, 1)
void scores_mma(const float* __restrict__ Yq, const float* __restrict__ Yk,
                const float* __restrict__ emd, float* __restrict__ sc) {
    extern __shared__ char sm[];
    const int tid = threadIdx.x;
    const int wid = tid >> 5, lane = tid & 31;
    const int bh = blockIdx.z, b = bh >> 4, h = bh & 15;
    const int s0 = blockIdx.y * 128, t0 = blockIdx.x * 128;
    const int wm = (wid & 1) * 64, wn = (wid >> 1) * 32;

    // load Q,K tiles (128 rows x 64 k) -> bf16 hi/lo
    const int lr = tid >> 1, lk = (tid & 1) * 32;
    const float* qp = Yq + (size_t)(b * SQ + s0 + lr) * DM + h * DH + lk;
    const float* kp = Yk + (size_t)(b * SQ + t0 + lr) * DM + h * DH + lk;
    const uint32_t so = (uint32_t)(lr * SC_STRIDE + lk) * 2;
    char* Ah = sm;
    char* Al = sm + SC_PART;
    char* Bh = sm + 2 * SC_PART;
    char* Bl = sm + 3 * SC_PART;
#pragma unroll
    for (int i = 0; i < 4; i++) {
        float4 v0 = *(const float4*)(qp + i * 8);
        float4 v1 = *(const float4*)(qp + i * 8 + 4);
        uint4 hh, ll;
        cvt_pack8(v0, v1, &hh, &ll);
        *(uint4*)(Ah + so + i * 16) = hh;
        *(uint4*)(Al + so + i * 16) = ll;
        v0 = *(const float4*)(kp + i * 8);
        v1 = *(const float4*)(kp + i * 8 + 4);
        cvt_pack8(v0, v1, &hh, &ll);
        *(uint4*)(Bh + so + i * 16) = hh;
        *(uint4*)(Bl + so + i * 16) = ll;
    }
    __syncthreads();

    float acc[4][4][4];
#pragma unroll
    for (int i = 0; i < 4; i++)
#pragma unroll
        for (int j = 0; j < 4; j++)
#pragma unroll
            for (int r = 0; r < 4; r++) acc[i][j][r] = 0.f;

    const uint32_t sb = smem_u32(sm);
    const uint32_t a_off = (uint32_t)((wm + (lane & 15)) * SC_STRIDE) * 2
                         + ((lane >> 4) & 1) * 16;
    const uint32_t b_off = (uint32_t)((wn + (lane & 7) + ((lane >> 4) & 1) * 8) * SC_STRIDE) * 2
                         + ((lane >> 3) & 1) * 16;

#pragma unroll
    for (int ks = 0; ks < 4; ks++) {
        uint32_t AhF[4][4], AlF[4][4], BhF[4][2], BlF[4][2];
#pragma unroll
        for (int mt = 0; mt < 4; mt++)
            ldsm4(sb + a_off + mt * (16 * SC_STRIDE * 2) + ks * 32, AhF[mt]);
#pragma unroll
        for (int mt = 0; mt < 4; mt++)
            ldsm4(sb + SC_PART + a_off + mt * (16 * SC_STRIDE * 2) + ks * 32, AlF[mt]);
#pragma unroll
        for (int bt = 0; bt < 2; bt++) {
            uint32_t r[4];
            ldsm4(sb + 2 * SC_PART + b_off + bt * (16 * SC_STRIDE * 2) + ks * 32, r);
            BhF[2 * bt][0] = r[0]; BhF[2 * bt][1] = r[1];
            BhF[2 * bt + 1][0] = r[2]; BhF[2 * bt + 1][1] = r[3];
        }
#pragma unroll
        for (int bt = 0; bt < 2; bt++) {
            uint32_t r[4];
            ldsm4(sb + 3 * SC_PART + b_off + bt * (16 * SC_STRIDE * 2) + ks * 32, r);
            BlF[2 * bt][0] = r[0]; BlF[2 * bt][1] = r[1];
            BlF[2 * bt + 1][0] = r[2]; BlF[2 * bt + 1][1] = r[3];
        }
#pragma unroll
        for (int mt = 0; mt < 4; mt++)
#pragma unroll
            for (int nt = 0; nt < 4; nt++)
                mma16816(acc[mt][nt], AhF[mt], BhF[nt]);
#pragma unroll
        for (int mt = 0; mt < 4; mt++)
#pragma unroll
            for (int nt = 0; nt < 4; nt++)
                mma16816(acc[mt][nt], AhF[mt], BlF[nt]);
#pragma unroll
        for (int mt = 0; mt < 4; mt++)
#pragma unroll
            for (int nt = 0; nt < 4; nt++)
                mma16816(acc[mt][nt], AlF[mt], BhF[nt]);
    }

    // epilogue: scale + skew band + store
    const int er = lane >> 2, ec = (lane & 3) * 2;
    const size_t base = (size_t)bh * SS;
#pragma unroll
    for (int mt = 0; mt < 4; mt++) {
#pragma unroll
        for (int nt = 0; nt < 4; nt++) {
            const int col = t0 + wn + nt * 8 + ec;
#pragma unroll
            for (int half = 0; half < 2; half++) {
                const int sg = s0 + wm + mt * 16 + er + half * 8;
                float v0 = 0.125f * acc[mt][nt][2 * half];
                float v1 = 0.125f * acc[mt][nt][2 * half + 1];
                const float* erow = emd + base + (size_t)sg * SQ;
                if (col     <= sg) v0 += erow[1023 + col     - sg];
                if (col + 1 <= sg) v1 += erow[1023 + col + 1 - sg];
                *(float2*)(sc + base + (size_t)sg * SQ + col) = make_float2(v0, v1);
            }
        }
    }
}

// ============================================================
// fused softmax(batch)+PV (HMMA): one CTA = (h, 64 s-rows), all 4 batches.
// t-chunks of 32; P,V split bf16 hi/lo in SMEM; 8 warps = 4b x 2 (32 rows).
// ============================================================
#define PV_PB 10240                   // per-b bytes (hi 5120 + lo 5120)
#define PV_V_BASE 40960
#define PV_SMEM 81920

__global__ __launch_bounds__(256, 1)
void pv_mma(const float* __restrict__ sc, const float* __restrict__ Yv,
            float* __restrict__ out) {
    extern __shared__ char sm[];
    const int tid = threadIdx.x;
    const int wid = tid >> 5, lane = tid & 31;
    const int s0 = blockIdx.x * 64;
    const int h  = blockIdx.y;

    float acc[2][8][4];
#pragma unroll
    for (int i = 0; i < 2; i++)
#pragma unroll
        for (int j = 0; j < 8; j++)
#pragma unroll
            for (int r = 0; r < 4; r++) acc[i][j][r] = 0.f;

    const int bq = wid >> 1, wm = (wid & 1) * 32;
    const uint32_t sb = smem_u32(sm);
    const uint32_t aBase = sb + (uint32_t)bq * PV_PB
                         + (uint32_t)((wm + (lane & 15)) * 80)
                         + ((lane >> 4) & 1) * 16;
    const uint32_t bBase = sb + PV_V_BASE + (uint32_t)bq * PV_PB
                         + (uint32_t)(((lane & 7) + ((lane >> 4) & 1) * 8) * 80)
                         + ((lane >> 3) & 1) * 16;

    for (int t0 = 0; t0 < SQ; t0 += 32) {
        // ---- P: load 4-batch scores, softmax over b, split bf16, store ----
#pragma unroll
        for (int i = 0; i < 4; i++) {
            const int e  = tid + i * 256;       // 0..1023
            const int s  = e >> 4;              // 0..63
            const int t2 = (e & 15) * 2;        // 0..30
            const size_t off = (size_t)(s0 + s) * SQ + t0 + t2;
            float2 v[4];
#pragma unroll
            for (int b = 0; b < 4; b++)
                v[b] = *(const float2*)(sc + (size_t)(b * NH + h) * SS + off);
            float m0 = fmaxf(fmaxf(v[0].x, v[1].x), fmaxf(v[2].x, v[3].x));
            float m1 = fmaxf(fmaxf(v[0].y, v[1].y), fmaxf(v[2].y, v[3].y));
            float e0[4], e1[4];
            float sum0 = 0.f, sum1 = 0.f;
#pragma unroll
            for (int b = 0; b < 4; b++) {
                e0[b] = __expf(v[b].x - m0); sum0 += e0[b];
                e1[b] = __expf(v[b].y - m1); sum1 += e1[b];
            }
            const float i0 = 1.f / sum0, i1 = 1.f / sum1;
            const uint32_t po = (uint32_t)(s * 80 + t2 * 2);
#pragma unroll
            for (int b = 0; b < 4; b++) {
                float p0 = e0[b] * i0, p1 = e1[b] * i1;
                __nv_bfloat162 hb = __floats2bfloat162_rn(p0, p1);
                float r0 = p0 - __bfloat162float(hb.x);
                float r1 = p1 - __bfloat162float(hb.y);
                __nv_bfloat162 lb = __floats2bfloat162_rn(r0, r1);
                *(uint32_t*)(sm + b * PV_PB + po)        = *(uint32_t*)&hb;
                *(uint32_t*)(sm + b * PV_PB + 5120 + po) = *(uint32_t*)&lb;
            }
        }
        // ---- V: load 32t x 64d per b, transpose to [d][t], split bf16 ----
#pragma unroll
        for (int j = 0; j < 2; j++) {
            const int f  = tid + j * 256;       // 0..511
            const int d  = f & 63;
            const int t4 = (f >> 6) * 4;        // 0,4,...,28
#pragma unroll
            for (int b = 0; b < 4; b++) {
                const float* vp = Yv + (size_t)(b * SQ + t0 + t4) * DM + h * DH + d;
                float v0 = vp[0];
                float v1 = vp[DM];
                float v2 = vp[2 * DM];
                float v3 = vp[3 * DM];
                __nv_bfloat162 h01 = __floats2bfloat162_rn(v0, v1);
                __nv_bfloat162 h23 = __floats2bfloat162_rn(v2, v3);
                __nv_bfloat162 l01 = __floats2bfloat162_rn(v0 - __bfloat162float(h01.x),
                                                           v1 - __bfloat162float(h01.y));
                __nv_bfloat162 l23 = __floats2bfloat162_rn(v2 - __bfloat162float(h23.x),
                                                           v3 - __bfloat162float(h23.y));
                char* vb = sm + PV_V_BASE + b * PV_PB;
                const uint32_t vo = (uint32_t)(d * 80 + t4 * 2);
                *(uint2*)(vb + vo)        = make_uint2(*(uint32_t*)&h01, *(uint32_t*)&h23);
                *(uint2*)(vb + 5120 + vo) = make_uint2(*(uint32_t*)&l01, *(uint32_t*)&l23);
            }
        }
        __syncthreads();

        // ---- MMA: P_b (32x32) x V_b (32->64) per warp ----
#pragma unroll
        for (int ks = 0; ks < 2; ks++) {
            uint32_t AhF[2][4], AlF[2][4], BhF[8][2], BlF[8][2];
#pragma unroll
            for (int mt = 0; mt < 2; mt++) {
                ldsm4(aBase + mt * 1280 + ks * 32, AhF[mt]);
                ldsm4(aBase + 5120 + mt * 1280 + ks * 32, AlF[mt]);
            }
#pragma unroll
            for (int bt = 0; bt < 4; bt++) {
                uint32_t r[4];
                ldsm4(bBase + bt * 1280 + ks * 32, r);
                BhF[2 * bt][0] = r[0]; BhF[2 * bt][1] = r[1];
                BhF[2 * bt + 1][0] = r[2]; BhF[2 * bt + 1][1] = r[3];
            }
#pragma unroll
            for (int bt = 0; bt < 4; bt++) {
                uint32_t r[4];
                ldsm4(bBase + 5120 + bt * 1280 + ks * 32, r);
                BlF[2 * bt][0] = r[0]; BlF[2 * bt][1] = r[1];
                BlF[2 * bt + 1][0] = r[2]; BlF[2 * bt + 1][1] = r[3];
            }
#pragma unroll
            for (int mt = 0; mt < 2; mt++)
#pragma unroll
                for (int nt = 0; nt < 8; nt++)
                    mma16816(acc[mt][nt], AhF[mt], BhF[nt]);
#pragma unroll
            for (int mt = 0; mt < 2; mt++)
#pragma unroll
                for (int nt = 0; nt < 8; nt++)
                    mma16816(acc[mt][nt], AhF[mt], BlF[nt]);
#pragma unroll
            for (int mt = 0; mt < 2; mt++)
#pragma unroll
                for (int nt = 0; nt < 8; nt++)
                    mma16816(acc[mt][nt], AlF[mt], BhF[nt]);
        }
        __syncthreads();
    }

    // epilogue: out[(bq*NH+h)*SQ + row][d]
    const int er = lane >> 2, ec = (lane & 3) * 2;
#pragma unroll
    for (int mt = 0; mt < 2; mt++) {
        const int row = s0 + wm + mt * 16 + er;
        float* op = out + ((size_t)(bq * NH + h) * SQ + row) * DH;
#pragma unroll
        for (int nt = 0; nt < 8; nt++) {
            const int col = nt * 8 + ec;
            *(float2*)(op + col)           = make_float2(acc[mt][nt][0], acc[mt][nt][1]);
            *(float2*)(op + 8 * DH + col)  = make_float2(acc[mt][nt][2], acc[mt][nt][3]);
        }
    }
}

// ============================================================
// residual + LayerNorm
// ============================================================
__device__ __forceinline__ float block_sum256(float v, float* red) {
#pragma unroll
    for (int o = 16; o > 0; o >>= 1) v += __shfl_xor_sync(0xffffffffu, v, o);
    int t = threadIdx.x;
    if ((t & 31) == 0) red[t >> 5] = v;
    __syncthreads();
    if (t == 0) {
        float s = 0.f;
#pragma unroll
        for (int i = 0; i < 8; i++) s += red[i];
        red[0] = s;
    }
    __syncthreads();
    float res = red[0];
    __syncthreads();
    return res;
}

__global__ __launch_bounds__(256)
void add_ln_kernel(const float* __restrict__ xa, const float* __restrict__ xb,
                   const float* __restrict__ g, const float* __restrict__ bb,
                   float* __restrict__ out) {
    const int row = blockIdx.x;
    const float* pa = xa + (size_t)row * DM;
    const float* pb = xb + (size_t)row * DM;
    __shared__ float red[8];
    const int t = threadIdx.x;

    float loc[4];
    float s = 0.f;
#pragma unroll
    for (int u = 0; u < 4; u++) {
        int i = t + u * 256;
        float v = pa[i] + pb[i];
        loc[u] = v;
        s += v;
    }
    float mean = block_sum256(s, red) * (1.f / 1024.f);

    float vs = 0.f;
#pragma unroll
    for (int u = 0; u < 4; u++) {
        float d = loc[u] - mean;
        vs += d * d;
    }
    float var = block_sum256(vs, red) * (1.f / 1024.f);
    float inv = rsqrtf(var + EPSV);

#pragma unroll
    for (int u = 0; u < 4; u++) {
        int i = t + u * 256;
        out[(size_t)row * DM + i] = (loc[u] - mean) * inv * g[i] + bb[i];
    }
}

// ============================================================
extern "C" void kernel_launch(void* const* d_in, const int* in_sizes, int n_in,
                              void* d_out, int out_size) {
    const float* x    = (const float*)d_in[0];
    const float* wq   = (const float*)d_in[1];
    const float* wk   = (const float*)d_in[2];
    const float* wv   = (const float*)d_in[3];
    const float* relw = (const float*)d_in[4];
    const float* ln1g = (const float*)d_in[5];
    const float* ln1b = (const float*)d_in[6];
    const float* ln2g = (const float*)d_in[7];
    const float* ln2b = (const float*)d_in[8];
    const float* w1   = (const float*)d_in[9];
    const float* b1   = (const float*)d_in[10];
    const float* w2   = (const float*)d_in[11];
    const float* b2   = (const float*)d_in[12];
    float* out = (float*)d_out;

    float *Yq, *Yk, *Yv, *emd, *sc, *att, *h1, *mid, *ffn;
    cudaGetSymbolAddress((void**)&Yq,  g_Yq);
    cudaGetSymbolAddress((void**)&Yk,  g_Yk);
    cudaGetSymbolAddress((void**)&Yv,  g_Yv);
    cudaGetSymbolAddress((void**)&emd, g_emd);
    cudaGetSymbolAddress((void**)&sc,  g_sc);
    cudaGetSymbolAddress((void**)&att, g_att);
    cudaGetSymbolAddress((void**)&h1,  g_h1);
    cudaGetSymbolAddress((void**)&mid, g_mid);
    cudaGetSymbolAddress((void**)&ffn, g_ffn);

    cudaFuncSetAttribute(mma_gemm<0, 0>, cudaFuncAttributeMaxDynamicSharedMemorySize, GSMEM);
    cudaFuncSetAttribute(mma_gemm<1, 1>, cudaFuncAttributeMaxDynamicSharedMemorySize, GSMEM);
    cudaFuncSetAttribute(mma_gemm<1, 0>, cudaFuncAttributeMaxDynamicSharedMemorySize, GSMEM);
    cudaFuncSetAttribute(scores_mma, cudaFuncAttributeMaxDynamicSharedMemorySize, SC_SMEM);
    cudaFuncSetAttribute(pv_mma, cudaFuncAttributeMaxDynamicSharedMemorySize, PV_SMEM);

    // QKV projections — HMMA bf16x2
    mma_gemm<0, 0><<<dim3(DM / 128, NROW / 128), 256, GSMEM>>>(x, wq, nullptr, Yq, DM, DM);
    mma_gemm<0, 0><<<dim3(DM / 128, NROW / 128), 256, GSMEM>>>(x, wk, nullptr, Yk, DM, DM);
    mma_gemm<0, 0><<<dim3(DM / 128, NROW / 128), 256, GSMEM>>>(x, wv, nullptr, Yv, DM, DM);

    // relative-position logits (live band only)
    emd_kernel<<<dim3(16, 16, 64), 256>>>(Yq, relw, emd);

    // attention scores + skew bias — HMMA
    scores_mma<<<dim3(8, 8, 64), 256, SC_SMEM>>>(Yq, Yk, emd, sc);

    // fused softmax(batch) + PV — HMMA
    pv_mma<<<dim3(16, 16), 256, PV_SMEM>>>(sc, Yv, att);

    // residual + LN1
    add_ln_kernel<<<NROW, 256>>>(x, att, ln1g, ln1b, h1);

    // FFN — HMMA bf16x2
    mma_gemm<1, 1><<<dim3(DFFN / 128, NROW / 128), 256, GSMEM>>>(h1, w1, b1, mid, DFFN, DM);
    mma_gemm<1, 0><<<dim3(DM / 128, NROW / 128), 256, GSMEM>>>(mid, w2, b2, ffn, DM, DFFN);

    // residual + LN2 -> output
    add_ln_kernel<<<NROW, 256>>>(h1, ffn, ln2g, ln2b, out);

    (void)in_sizes; (void)n_in; (void)out_size;
}

// round 9
// speedup vs baseline: 2.3170x; 1.0831x over previous
#include <cuda_runtime.h>
#include <cuda_bf16.h>
#include <math.h>
#include <stdint.h>

// Problem constants
#define SQ   1024
#define NB   4
#define DM   1024
#define NH   16
#define DH   64
#define DFFN 4096
#define NROW 4096          // S*B rows
#define EPSV 1e-5f
#define SS   1048576       // S*S

// ---- scratch (static device globals; no allocation allowed) ----
static __device__ float g_Yq[NROW * DM];
static __device__ float g_Yk[NROW * DM];
static __device__ float g_Yv[NROW * DM];
static __device__ float g_emd[67108864];   // (B,H,S,S) band
static __device__ float g_att[NROW * DM];
static __device__ float g_h1 [NROW * DM];
static __device__ float g_mid[NROW * DFFN];
static __device__ float g_ffn[NROW * DM];

// ============================================================
// common helpers
// ============================================================
__device__ __forceinline__ uint32_t smem_u32(const void* p) {
    uint32_t a;
    asm("{ .reg .u64 t; cvta.to.shared.u64 t, %1; cvt.u32.u64 %0, t; }"
        : "=r"(a) : "l"(p));
    return a;
}

__device__ __forceinline__ void ldsm4(uint32_t addr, uint32_t* r) {
    asm volatile("ldmatrix.sync.aligned.m8n8.x4.shared.b16 {%0,%1,%2,%3}, [%4];"
                 : "=r"(r[0]), "=r"(r[1]), "=r"(r[2]), "=r"(r[3])
                 : "r"(addr));
}

__device__ __forceinline__ void mma16816(float* c, const uint32_t* a, const uint32_t* b) {
    asm volatile(
        "mma.sync.aligned.m16n8k16.row.col.f32.bf16.bf16.f32 "
        "{%0,%1,%2,%3},{%4,%5,%6,%7},{%8,%9},{%0,%1,%2,%3};"
        : "+f"(c[0]), "+f"(c[1]), "+f"(c[2]), "+f"(c[3])
        : "r"(a[0]), "r"(a[1]), "r"(a[2]), "r"(a[3]), "r"(b[0]), "r"(b[1]));
}

// 8 fp32 -> 4 packed bf16x2 hi + 4 lo
__device__ __forceinline__ void cvt_pack8(const float4 v0, const float4 v1,
                                          uint4* hi, uint4* lo) {
    float f[8] = {v0.x, v0.y, v0.z, v0.w, v1.x, v1.y, v1.z, v1.w};
    uint32_t h[4], l[4];
#pragma unroll
    for (int i = 0; i < 4; i++) {
        __nv_bfloat162 hb = __floats2bfloat162_rn(f[2 * i], f[2 * i + 1]);
        float r0 = f[2 * i]     - __bfloat162float(hb.x);
        float r1 = f[2 * i + 1] - __bfloat162float(hb.y);
        __nv_bfloat162 lb = __floats2bfloat162_rn(r0, r1);
        h[i] = *(uint32_t*)&hb;
        l[i] = *(uint32_t*)&lb;
    }
    *hi = make_uint4(h[0], h[1], h[2], h[3]);
    *lo = make_uint4(l[0], l[1], l[2], l[3]);
}

// ============================================================
// mma.sync bf16x2 split GEMM: C[M,N] = A[M,K] @ B[N,K]^T (+bias)(+relu)
// CTA tile 128x128, BK=32, 256 thr (8 warps, 2m x 4n), warp tile 64x32.
// ============================================================
#define ASTRIDE 40
#define PART_BYTES (128 * ASTRIDE * 2)
#define STAGE_B (4 * PART_BYTES)
#define GSMEM (2 * STAGE_B)

template<int DO_BIAS, int DO_RELU>
__global__ __launch_bounds__(256, 1)
void mma_gemm(const float* __restrict__ A, const float* __restrict__ B,
              const float* __restrict__ bias, float* __restrict__ C,
              int N, int K) {
    extern __shared__ char sm[];
    const int tid  = threadIdx.x;
    const int wid  = tid >> 5, lane = tid & 31;
    const int m0 = blockIdx.y * 128, n0 = blockIdx.x * 128;
    const int wm = (wid & 1) * 64, wn = (wid >> 1) * 32;

    float acc[4][4][4];
#pragma unroll
    for (int i = 0; i < 4; i++)
#pragma unroll
        for (int j = 0; j < 4; j++)
#pragma unroll
            for (int r = 0; r < 4; r++) acc[i][j][r] = 0.f;

    const int lr = tid >> 1;
    const int lk = (tid & 1) * 16;
    const float* Ap = A + (size_t)(m0 + lr) * K + lk;
    const float* Bp = B + (size_t)(n0 + lr) * K + lk;
    const uint32_t sts_off = (uint32_t)(lr * ASTRIDE + lk) * 2;

    const uint32_t sb0 = smem_u32(sm);
    const uint32_t a_row_off = (uint32_t)((wm + (lane & 15)) * ASTRIDE) * 2
                             + ((lane >> 4) & 1) * 16;
    const uint32_t b_row_off = (uint32_t)((wn + (lane & 7) + ((lane >> 4) & 1) * 8) * ASTRIDE) * 2
                             + ((lane >> 3) & 1) * 16;

    const int NC = K >> 5;
    float4 stg[8];

#pragma unroll
    for (int i = 0; i < 4; i++) stg[i]     = *(const float4*)(Ap + i * 4);
#pragma unroll
    for (int i = 0; i < 4; i++) stg[4 + i] = *(const float4*)(Bp + i * 4);
    {
        char* st = sm;
        uint4 h0, l0, h1, l1;
        cvt_pack8(stg[0], stg[1], &h0, &l0);
        cvt_pack8(stg[2], stg[3], &h1, &l1);
        *(uint4*)(st + sts_off)                   = h0;
        *(uint4*)(st + sts_off + 16)              = h1;
        *(uint4*)(st + PART_BYTES + sts_off)      = l0;
        *(uint4*)(st + PART_BYTES + sts_off + 16) = l1;
        cvt_pack8(stg[4], stg[5], &h0, &l0);
        cvt_pack8(stg[6], stg[7], &h1, &l1);
        *(uint4*)(st + 2 * PART_BYTES + sts_off)      = h0;
        *(uint4*)(st + 2 * PART_BYTES + sts_off + 16) = h1;
        *(uint4*)(st + 3 * PART_BYTES + sts_off)      = l0;
        *(uint4*)(st + 3 * PART_BYTES + sts_off + 16) = l1;
    }
    __syncthreads();

    for (int c = 0; c < NC; c++) {
        if (c + 1 < NC) {
            const int kc = (c + 1) << 5;
#pragma unroll
            for (int i = 0; i < 4; i++) stg[i]     = *(const float4*)(Ap + kc + i * 4);
#pragma unroll
            for (int i = 0; i < 4; i++) stg[4 + i] = *(const float4*)(Bp + kc + i * 4);
        }
        {
            const uint32_t sbase = sb0 + (uint32_t)(c & 1) * STAGE_B;
            const uint32_t aA = sbase + a_row_off;
            const uint32_t aB = sbase + 2 * PART_BYTES + b_row_off;
#pragma unroll
            for (int ks = 0; ks < 2; ks++) {
                uint32_t Ah[4][4], Al[4][4], Bh[4][2], Bl[4][2];
#pragma unroll
                for (int mt = 0; mt < 4; mt++)
                    ldsm4(aA + mt * 1280 + ks * 32, Ah[mt]);
#pragma unroll
                for (int mt = 0; mt < 4; mt++)
                    ldsm4(aA + PART_BYTES + mt * 1280 + ks * 32, Al[mt]);
#pragma unroll
                for (int bt = 0; bt < 2; bt++) {
                    uint32_t r[4];
                    ldsm4(aB + bt * 1280 + ks * 32, r);
                    Bh[2 * bt][0] = r[0]; Bh[2 * bt][1] = r[1];
                    Bh[2 * bt + 1][0] = r[2]; Bh[2 * bt + 1][1] = r[3];
                }
#pragma unroll
                for (int bt = 0; bt < 2; bt++) {
                    uint32_t r[4];
                    ldsm4(aB + PART_BYTES + bt * 1280 + ks * 32, r);
                    Bl[2 * bt][0] = r[0]; Bl[2 * bt][1] = r[1];
                    Bl[2 * bt + 1][0] = r[2]; Bl[2 * bt + 1][1] = r[3];
                }
#pragma unroll
                for (int mt = 0; mt < 4; mt++)
#pragma unroll
                    for (int nt = 0; nt < 4; nt++)
                        mma16816(acc[mt][nt], Ah[mt], Bh[nt]);
#pragma unroll
                for (int mt = 0; mt < 4; mt++)
#pragma unroll
                    for (int nt = 0; nt < 4; nt++)
                        mma16816(acc[mt][nt], Ah[mt], Bl[nt]);
#pragma unroll
                for (int mt = 0; mt < 4; mt++)
#pragma unroll
                    for (int nt = 0; nt < 4; nt++)
                        mma16816(acc[mt][nt], Al[mt], Bh[nt]);
            }
        }
        if (c + 1 < NC) {
            char* st = sm + ((c + 1) & 1) * STAGE_B;
            uint4 h0, l0, h1, l1;
            cvt_pack8(stg[0], stg[1], &h0, &l0);
            cvt_pack8(stg[2], stg[3], &h1, &l1);
            *(uint4*)(st + sts_off)                   = h0;
            *(uint4*)(st + sts_off + 16)              = h1;
            *(uint4*)(st + PART_BYTES + sts_off)      = l0;
            *(uint4*)(st + PART_BYTES + sts_off + 16) = l1;
            cvt_pack8(stg[4], stg[5], &h0, &l0);
            cvt_pack8(stg[6], stg[7], &h1, &l1);
            *(uint4*)(st + 2 * PART_BYTES + sts_off)      = h0;
            *(uint4*)(st + 2 * PART_BYTES + sts_off + 16) = h1;
            *(uint4*)(st + 3 * PART_BYTES + sts_off)      = l0;
            *(uint4*)(st + 3 * PART_BYTES + sts_off + 16) = l1;
        }
        __syncthreads();
    }

    const int er = lane >> 2, ec = (lane & 3) * 2;
#pragma unroll
    for (int mt = 0; mt < 4; mt++) {
        const int row0 = m0 + wm + mt * 16 + er;
#pragma unroll
        for (int nt = 0; nt < 4; nt++) {
            const int col = n0 + wn + nt * 8 + ec;
            float2 bv = make_float2(0.f, 0.f);
            if (DO_BIAS) bv = *(const float2*)(bias + col);
            float2 o0, o1;
            o0.x = acc[mt][nt][0] + bv.x; o0.y = acc[mt][nt][1] + bv.y;
            o1.x = acc[mt][nt][2] + bv.x; o1.y = acc[mt][nt][3] + bv.y;
            if (DO_RELU) {
                o0.x = fmaxf(o0.x, 0.f); o0.y = fmaxf(o0.y, 0.f);
                o1.x = fmaxf(o1.x, 0.f); o1.y = fmaxf(o1.y, 0.f);
            }
            *(float2*)(C + (size_t)row0 * N + col)       = o0;
            *(float2*)(C + (size_t)(row0 + 8) * N + col) = o1;
        }
    }
}

// ============================================================
// emd (HMMA): emd[b,h,s,j] = sum_i Q[b,h,s,i]*relw[b,h,i,j]
// 128x128 tiles, K=64, bf16x2 split. Only band s+j>=1023 is live.
// relw transposed to [j][i] via fp32 SMEM scratch (coalesced).
// ============================================================
#define EM_STRIDE 72
#define EM_PART (128 * EM_STRIDE * 2)   // 18432
#define EM_SCR  (4 * EM_PART)           // scratch at 73728
#define EM_SMEM (4 * EM_PART + 64 * 132 * 4)   // 107520

__global__ __launch_bounds__(256, 1)
void emd_mma(const float* __restrict__ Yq, const float* __restrict__ relw,
             float* __restrict__ emd) {
    const int bh = blockIdx.z, b = bh >> 4, h = bh & 15;
    const int s0 = blockIdx.y * 128, j0 = blockIdx.x * 128;
    if (s0 + j0 < 769) return;   // tile fully below the live band
    extern __shared__ char sm[];
    float* scr = (float*)(sm + EM_SCR);
    const int tid = threadIdx.x;
    const int wid = tid >> 5, lane = tid & 31;
    const int wm = (wid & 1) * 64, wn = (wid >> 1) * 32;

    // A (Q tile): 128 s x 64 i -> hi/lo
    {
        const int lr = tid >> 1, lk = (tid & 1) * 32;
        const float* qp = Yq + (size_t)(b * SQ + s0 + lr) * DM + h * DH + lk;
        const uint32_t so = (uint32_t)(lr * EM_STRIDE + lk) * 2;
#pragma unroll
        for (int i = 0; i < 4; i++) {
            float4 v0 = *(const float4*)(qp + i * 8);
            float4 v1 = *(const float4*)(qp + i * 8 + 4);
            uint4 hh, ll;
            cvt_pack8(v0, v1, &hh, &ll);
            *(uint4*)(sm + so + i * 16)           = hh;
            *(uint4*)(sm + EM_PART + so + i * 16) = ll;
        }
    }
    // B stage1: coalesced relw [i][j] -> fp32 scratch
#pragma unroll
    for (int it = 0; it < 8; it++) {
        int f = tid + it * 256;          // 0..2047
        int i = f >> 5, jf = (f & 31) * 4;
        float4 v = *(const float4*)(relw + ((size_t)bh * DH + i) * SQ + j0 + jf);
        *(float4*)(scr + i * 132 + jf) = v;
    }
    __syncthreads();
    // B stage2: transpose + split -> [j][i] hi/lo
#pragma unroll
    for (int it = 0; it < 8; it++) {
        int u = tid + it * 256;          // 0..2047
        int j = u & 127, i4 = (u >> 7) * 4;
        float f0 = scr[(i4 + 0) * 132 + j];
        float f1 = scr[(i4 + 1) * 132 + j];
        float f2 = scr[(i4 + 2) * 132 + j];
        float f3 = scr[(i4 + 3) * 132 + j];
        __nv_bfloat162 h01 = __floats2bfloat162_rn(f0, f1);
        __nv_bfloat162 h23 = __floats2bfloat162_rn(f2, f3);
        __nv_bfloat162 l01 = __floats2bfloat162_rn(f0 - __bfloat162float(h01.x),
                                                   f1 - __bfloat162float(h01.y));
        __nv_bfloat162 l23 = __floats2bfloat162_rn(f2 - __bfloat162float(h23.x),
                                                   f3 - __bfloat162float(h23.y));
        const uint32_t o = (uint32_t)(j * 144 + i4 * 2);
        *(uint2*)(sm + 2 * EM_PART + o) = make_uint2(*(uint32_t*)&h01, *(uint32_t*)&h23);
        *(uint2*)(sm + 3 * EM_PART + o) = make_uint2(*(uint32_t*)&l01, *(uint32_t*)&l23);
    }
    __syncthreads();

    float acc[4][4][4];
#pragma unroll
    for (int i = 0; i < 4; i++)
#pragma unroll
        for (int j = 0; j < 4; j++)
#pragma unroll
            for (int r = 0; r < 4; r++) acc[i][j][r] = 0.f;

    const uint32_t sb = smem_u32(sm);
    const uint32_t a_off = (uint32_t)((wm + (lane & 15)) * EM_STRIDE) * 2
                         + ((lane >> 4) & 1) * 16;
    const uint32_t b_off = (uint32_t)((wn + (lane & 7) + ((lane >> 4) & 1) * 8) * EM_STRIDE) * 2
                         + ((lane >> 3) & 1) * 16;

#pragma unroll
    for (int ks = 0; ks < 4; ks++) {
        uint32_t AhF[4][4], AlF[4][4], BhF[4][2], BlF[4][2];
#pragma unroll
        for (int mt = 0; mt < 4; mt++)
            ldsm4(sb + a_off + mt * 2304 + ks * 32, AhF[mt]);
#pragma unroll
        for (int mt = 0; mt < 4; mt++)
            ldsm4(sb + EM_PART + a_off + mt * 2304 + ks * 32, AlF[mt]);
#pragma unroll
        for (int bt = 0; bt < 2; bt++) {
            uint32_t r[4];
            ldsm4(sb + 2 * EM_PART + b_off + bt * 2304 + ks * 32, r);
            BhF[2 * bt][0] = r[0]; BhF[2 * bt][1] = r[1];
            BhF[2 * bt + 1][0] = r[2]; BhF[2 * bt + 1][1] = r[3];
        }
#pragma unroll
        for (int bt = 0; bt < 2; bt++) {
            uint32_t r[4];
            ldsm4(sb + 3 * EM_PART + b_off + bt * 2304 + ks * 32, r);
            BlF[2 * bt][0] = r[0]; BlF[2 * bt][1] = r[1];
            BlF[2 * bt + 1][0] = r[2]; BlF[2 * bt + 1][1] = r[3];
        }
#pragma unroll
        for (int mt = 0; mt < 4; mt++)
#pragma unroll
            for (int nt = 0; nt < 4; nt++)
                mma16816(acc[mt][nt], AhF[mt], BhF[nt]);
#pragma unroll
        for (int mt = 0; mt < 4; mt++)
#pragma unroll
            for (int nt = 0; nt < 4; nt++)
                mma16816(acc[mt][nt], AhF[mt], BlF[nt]);
#pragma unroll
        for (int mt = 0; mt < 4; mt++)
#pragma unroll
            for (int nt = 0; nt < 4; nt++)
                mma16816(acc[mt][nt], AlF[mt], BhF[nt]);
    }

    const int er = lane >> 2, ec = (lane & 3) * 2;
#pragma unroll
    for (int mt = 0; mt < 4; mt++) {
#pragma unroll
        for (int nt = 0; nt < 4; nt++) {
            const int col = j0 + wn + nt * 8 + ec;
#pragma unroll
            for (int half = 0; half < 2; half++) {
                const int sg = s0 + wm + mt * 16 + er + half * 8;
                *(float2*)(emd + (size_t)bh * SS + (size_t)sg * SQ + col) =
                    make_float2(acc[mt][nt][2 * half], acc[mt][nt][2 * half + 1]);
            }
        }
    }
}

// ============================================================
// fused attention: scores(QK^T*0.125 + skew) -> softmax over batch -> PV
// CTA = (s-block 64, head). 8 warps = 4b x 2 (32 s-rows). t-chunks of 64.
// Regions: KV [4b][hi|lo 64x144B], SC fp32 [4b][64][72f], P [4b][hi|lo].
// ============================================================
#define FA_B 18432
#define FA_SC_OFF 73728
#define FA_P_OFF  147456
#define FA_SMEM   221184

__global__ __launch_bounds__(256, 1)
void fused_attn(const float* __restrict__ Yq, const float* __restrict__ Yk,
                const float* __restrict__ Yv, const float* __restrict__ emd,
                float* __restrict__ out) {
    extern __shared__ char sm[];
    char* smKV = sm;
    char* smSC = sm + FA_SC_OFF;
    char* smP  = sm + FA_P_OFF;
    const int tid = threadIdx.x;
    const int wid = tid >> 5, lane = tid & 31;
    const int s0 = blockIdx.x * 64;
    const int h  = blockIdx.y;
    const int bq = wid >> 1;
    const int wm = (wid & 1) * 32;
    const int er = lane >> 2, ec = (lane & 3) * 2;

    const uint32_t sb = smem_u32(sm);
    const int lr = tid >> 1;
    const int lk = (tid & 1) * 32;

    // ---- stage Q (4b x 64s x 64k) into KV region ----
#pragma unroll
    for (int it = 0; it < 2; it++) {
        int row = lr + it * 128;
        int b = row >> 6, r = row & 63;
        const float* p = Yq + (size_t)(b * SQ + s0 + r) * DM + h * DH + lk;
        char* dst = smKV + b * FA_B + r * 144 + lk * 2;
#pragma unroll
        for (int i = 0; i < 2; i++) {
            float4 v0 = *(const float4*)(p + i * 16);
            float4 v1 = *(const float4*)(p + i * 16 + 4);
            float4 v2 = *(const float4*)(p + i * 16 + 8);
            float4 v3 = *(const float4*)(p + i * 16 + 12);
            uint4 h0, l0, h1, l1;
            cvt_pack8(v0, v1, &h0, &l0);
            cvt_pack8(v2, v3, &h1, &l1);
            *(uint4*)(dst + i * 32)              = h0;
            *(uint4*)(dst + i * 32 + 16)         = h1;
            *(uint4*)(dst + 9216 + i * 32)       = l0;
            *(uint4*)(dst + 9216 + i * 32 + 16)  = l1;
        }
    }
    __syncthreads();

    // ---- Q fragments (register-resident for the whole loop) ----
    uint32_t Qh[2][4][4], Ql[2][4][4];
    {
        const uint32_t aQ = sb + (uint32_t)bq * FA_B + (wm + (lane & 15)) * 144
                          + ((lane >> 4) & 1) * 16;
#pragma unroll
        for (int mt = 0; mt < 2; mt++)
#pragma unroll
            for (int ks = 0; ks < 4; ks++) {
                ldsm4(aQ + mt * 2304 + ks * 32, Qh[mt][ks]);
                ldsm4(aQ + 9216 + mt * 2304 + ks * 32, Ql[mt][ks]);
            }
    }

    float oacc[2][8][4];
#pragma unroll
    for (int i = 0; i < 2; i++)
#pragma unroll
        for (int j = 0; j < 8; j++)
#pragma unroll
            for (int r = 0; r < 4; r++) oacc[i][j][r] = 0.f;

    const uint32_t kvB = sb + (uint32_t)bq * FA_B
                       + ((lane & 7) + ((lane >> 4) & 1) * 8) * 144
                       + ((lane >> 3) & 1) * 16;
    const uint32_t aP = sb + FA_P_OFF + (uint32_t)bq * FA_B
                      + (wm + (lane & 15)) * 144 + ((lane >> 4) & 1) * 16;
    const size_t ebase = (size_t)(bq * NH + h) * SS;

    for (int t0 = 0; t0 < SQ; t0 += 64) {
        __syncthreads();   // KV free (prev PV ldsm done / Q frags extracted)

        // ---- load K chunk (4b x 64t x 64k) -> KV ----
#pragma unroll
        for (int it = 0; it < 2; it++) {
            int row = lr + it * 128;
            int b = row >> 6, r = row & 63;
            const float* p = Yk + (size_t)(b * SQ + t0 + r) * DM + h * DH + lk;
            char* dst = smKV + b * FA_B + r * 144 + lk * 2;
#pragma unroll
            for (int i = 0; i < 2; i++) {
                float4 v0 = *(const float4*)(p + i * 16);
                float4 v1 = *(const float4*)(p + i * 16 + 4);
                float4 v2 = *(const float4*)(p + i * 16 + 8);
                float4 v3 = *(const float4*)(p + i * 16 + 12);
                uint4 h0, l0, h1, l1;
                cvt_pack8(v0, v1, &h0, &l0);
                cvt_pack8(v2, v3, &h1, &l1);
                *(uint4*)(dst + i * 32)              = h0;
                *(uint4*)(dst + i * 32 + 16)         = h1;
                *(uint4*)(dst + 9216 + i * 32)       = l0;
                *(uint4*)(dst + 9216 + i * 32 + 16)  = l1;
            }
        }
        __syncthreads();

        // ---- QK MMA ----
        float qk[2][8][4];
#pragma unroll
        for (int i = 0; i < 2; i++)
#pragma unroll
            for (int j = 0; j < 8; j++)
#pragma unroll
                for (int r = 0; r < 4; r++) qk[i][j][r] = 0.f;
#pragma unroll
        for (int ks = 0; ks < 4; ks++) {
            uint32_t Bh[8][2], Bl[8][2];
#pragma unroll
            for (int bt = 0; bt < 4; bt++) {
                uint32_t r[4];
                ldsm4(kvB + bt * 2304 + ks * 32, r);
                Bh[2 * bt][0] = r[0]; Bh[2 * bt][1] = r[1];
                Bh[2 * bt + 1][0] = r[2]; Bh[2 * bt + 1][1] = r[3];
            }
#pragma unroll
            for (int bt = 0; bt < 4; bt++) {
                uint32_t r[4];
                ldsm4(kvB + 9216 + bt * 2304 + ks * 32, r);
                Bl[2 * bt][0] = r[0]; Bl[2 * bt][1] = r[1];
                Bl[2 * bt + 1][0] = r[2]; Bl[2 * bt + 1][1] = r[3];
            }
#pragma unroll
            for (int mt = 0; mt < 2; mt++)
#pragma unroll
                for (int nt = 0; nt < 8; nt++)
                    mma16816(qk[mt][nt], Qh[mt][ks], Bh[nt]);
#pragma unroll
            for (int mt = 0; mt < 2; mt++)
#pragma unroll
                for (int nt = 0; nt < 8; nt++)
                    mma16816(qk[mt][nt], Qh[mt][ks], Bl[nt]);
#pragma unroll
            for (int mt = 0; mt < 2; mt++)
#pragma unroll
                for (int nt = 0; nt < 8; nt++)
                    mma16816(qk[mt][nt], Ql[mt][ks], Bh[nt]);
        }

        // ---- scale + skew + write SC ----
#pragma unroll
        for (int mt = 0; mt < 2; mt++) {
#pragma unroll
            for (int nt = 0; nt < 8; nt++) {
                const int tg = nt * 8 + ec;
                const int tgl = t0 + tg;
#pragma unroll
                for (int half = 0; half < 2; half++) {
                    const int sg = wm + mt * 16 + er + half * 8;
                    const int sgl = s0 + sg;
                    float v0 = 0.125f * qk[mt][nt][2 * half];
                    float v1 = 0.125f * qk[mt][nt][2 * half + 1];
                    if (tgl <= sgl)
                        v0 += emd[ebase + (size_t)sgl * SQ + 1023 + tgl - sgl];
                    if (tgl + 1 <= sgl)
                        v1 += emd[ebase + (size_t)sgl * SQ + 1024 + tgl - sgl];
                    *(float2*)(smSC + bq * FA_B + sg * 288 + tg * 4) = make_float2(v0, v1);
                }
            }
        }
        __syncthreads();

        // ---- softmax over batch -> P (bf16 hi/lo) ----
#pragma unroll
        for (int i = 0; i < 8; i++) {
            const int e = tid + i * 256;
            const int s = e >> 5, t2 = (e & 31) * 2;
            float2 v[4];
#pragma unroll
            for (int b = 0; b < 4; b++)
                v[b] = *(const float2*)(smSC + b * FA_B + s * 288 + t2 * 4);
            float m0 = fmaxf(fmaxf(v[0].x, v[1].x), fmaxf(v[2].x, v[3].x));
            float m1 = fmaxf(fmaxf(v[0].y, v[1].y), fmaxf(v[2].y, v[3].y));
            float e0[4], e1[4];
            float sum0 = 0.f, sum1 = 0.f;
#pragma unroll
            for (int b = 0; b < 4; b++) {
                e0[b] = __expf(v[b].x - m0); sum0 += e0[b];
                e1[b] = __expf(v[b].y - m1); sum1 += e1[b];
            }
            const float i0 = 1.f / sum0, i1 = 1.f / sum1;
#pragma unroll
            for (int b = 0; b < 4; b++) {
                float p0 = e0[b] * i0, p1 = e1[b] * i1;
                __nv_bfloat162 hb = __floats2bfloat162_rn(p0, p1);
                float r0 = p0 - __bfloat162float(hb.x);
                float r1 = p1 - __bfloat162float(hb.y);
                __nv_bfloat162 lb = __floats2bfloat162_rn(r0, r1);
                *(uint32_t*)(smP + b * FA_B + s * 144 + t2 * 2)        = *(uint32_t*)&hb;
                *(uint32_t*)(smP + b * FA_B + 9216 + s * 144 + t2 * 2) = *(uint32_t*)&lb;
            }
        }
        // ---- load V chunk transposed [d][t] -> KV ----
#pragma unroll
        for (int it = 0; it < 4; it++) {
            const int f = tid + it * 256;
            const int d = f & 63;
            const int t4 = (f >> 6) * 4;
#pragma unroll
            for (int b = 0; b < 4; b++) {
                const float* vp = Yv + (size_t)(b * SQ + t0 + t4) * DM + h * DH + d;
                float v0 = vp[0];
                float v1 = vp[DM];
                float v2 = vp[2 * DM];
                float v3 = vp[3 * DM];
                __nv_bfloat162 h01 = __floats2bfloat162_rn(v0, v1);
                __nv_bfloat162 h23 = __floats2bfloat162_rn(v2, v3);
                __nv_bfloat162 l01 = __floats2bfloat162_rn(v0 - __bfloat162float(h01.x),
                                                           v1 - __bfloat162float(h01.y));
                __nv_bfloat162 l23 = __floats2bfloat162_rn(v2 - __bfloat162float(h23.x),
                                                           v3 - __bfloat162float(h23.y));
                char* vb = smKV + b * FA_B;
                const uint32_t vo = (uint32_t)(d * 144 + t4 * 2);
                *(uint2*)(vb + vo)        = make_uint2(*(uint32_t*)&h01, *(uint32_t*)&h23);
                *(uint2*)(vb + 9216 + vo) = make_uint2(*(uint32_t*)&l01, *(uint32_t*)&l23);
            }
        }
        __syncthreads();

        // ---- PV MMA ----
#pragma unroll
        for (int ks = 0; ks < 4; ks++) {
            uint32_t Ph[2][4], Pl[2][4], Vh[8][2], Vl[8][2];
#pragma unroll
            for (int mt = 0; mt < 2; mt++) {
                ldsm4(aP + mt * 2304 + ks * 32, Ph[mt]);
                ldsm4(aP + 9216 + mt * 2304 + ks * 32, Pl[mt]);
            }
#pragma unroll
            for (int bt = 0; bt < 4; bt++) {
                uint32_t r[4];
                ldsm4(kvB + bt * 2304 + ks * 32, r);
                Vh[2 * bt][0] = r[0]; Vh[2 * bt][1] = r[1];
                Vh[2 * bt + 1][0] = r[2]; Vh[2 * bt + 1][1] = r[3];
            }
#pragma unroll
            for (int bt = 0; bt < 4; bt++) {
                uint32_t r[4];
                ldsm4(kvB + 9216 + bt * 2304 + ks * 32, r);
                Vl[2 * bt][0] = r[0]; Vl[2 * bt][1] = r[1];
                Vl[2 * bt + 1][0] = r[2]; Vl[2 * bt + 1][1] = r[3];
            }
#pragma unroll
            for (int mt = 0; mt < 2; mt++)
#pragma unroll
                for (int nt = 0; nt < 8; nt++)
                    mma16816(oacc[mt][nt], Ph[mt], Vh[nt]);
#pragma unroll
            for (int mt = 0; mt < 2; mt++)
#pragma unroll
                for (int nt = 0; nt < 8; nt++)
                    mma16816(oacc[mt][nt], Ph[mt], Vl[nt]);
#pragma unroll
            for (int mt = 0; mt < 2; mt++)
#pragma unroll
                for (int nt = 0; nt < 8; nt++)
                    mma16816(oacc[mt][nt], Pl[mt], Vh[nt]);
        }
    }

    // ---- epilogue: out[(bq*NH+h)*SQ + row][d] ----
#pragma unroll
    for (int mt = 0; mt < 2; mt++) {
        const int row = s0 + wm + mt * 16 + er;
        float* op = out + ((size_t)(bq * NH + h) * SQ + row) * DH;
#pragma unroll
        for (int nt = 0; nt < 8; nt++) {
            const int col = nt * 8 + ec;
            *(float2*)(op + col)          = make_float2(oacc[mt][nt][0], oacc[mt][nt][1]);
            *(float2*)(op + 8 * DH + col) = make_float2(oacc[mt][nt][2], oacc[mt][nt][3]);
        }
    }
}

// ============================================================
// residual + LayerNorm
// ============================================================
__device__ __forceinline__ float block_sum256(float v, float* red) {
#pragma unroll
    for (int o = 16; o > 0; o >>= 1) v += __shfl_xor_sync(0xffffffffu, v, o);
    int t = threadIdx.x;
    if ((t & 31) == 0) red[t >> 5] = v;
    __syncthreads();
    if (t == 0) {
        float s = 0.f;
#pragma unroll
        for (int i = 0; i < 8; i++) s += red[i];
        red[0] = s;
    }
    __syncthreads();
    float res = red[0];
    __syncthreads();
    return res;
}

__global__ __launch_bounds__(256)
void add_ln_kernel(const float* __restrict__ xa, const float* __restrict__ xb,
                   const float* __restrict__ g, const float* __restrict__ bb,
                   float* __restrict__ out) {
    const int row = blockIdx.x;
    const float* pa = xa + (size_t)row * DM;
    const float* pb = xb + (size_t)row * DM;
    __shared__ float red[8];
    const int t = threadIdx.x;

    float loc[4];
    float s = 0.f;
#pragma unroll
    for (int u = 0; u < 4; u++) {
        int i = t + u * 256;
        float v = pa[i] + pb[i];
        loc[u] = v;
        s += v;
    }
    float mean = block_sum256(s, red) * (1.f / 1024.f);

    float vs = 0.f;
#pragma unroll
    for (int u = 0; u < 4; u++) {
        float d = loc[u] - mean;
        vs += d * d;
    }
    float var = block_sum256(vs, red) * (1.f / 1024.f);
    float inv = rsqrtf(var + EPSV);

#pragma unroll
    for (int u = 0; u < 4; u++) {
        int i = t + u * 256;
        out[(size_t)row * DM + i] = (loc[u] - mean) * inv * g[i] + bb[i];
    }
}

// ============================================================
extern "C" void kernel_launch(void* const* d_in, const int* in_sizes, int n_in,
                              void* d_out, int out_size) {
    const float* x    = (const float*)d_in[0];
    const float* wq   = (const float*)d_in[1];
    const float* wk   = (const float*)d_in[2];
    const float* wv   = (const float*)d_in[3];
    const float* relw = (const float*)d_in[4];
    const float* ln1g = (const float*)d_in[5];
    const float* ln1b = (const float*)d_in[6];
    const float* ln2g = (const float*)d_in[7];
    const float* ln2b = (const float*)d_in[8];
    const float* w1   = (const float*)d_in[9];
    const float* b1   = (const float*)d_in[10];
    const float* w2   = (const float*)d_in[11];
    const float* b2   = (const float*)d_in[12];
    float* out = (float*)d_out;

    float *Yq, *Yk, *Yv, *emd, *att, *h1, *mid, *ffn;
    cudaGetSymbolAddress((void**)&Yq,  g_Yq);
    cudaGetSymbolAddress((void**)&Yk,  g_Yk);
    cudaGetSymbolAddress((void**)&Yv,  g_Yv);
    cudaGetSymbolAddress((void**)&emd, g_emd);
    cudaGetSymbolAddress((void**)&att, g_att);
    cudaGetSymbolAddress((void**)&h1,  g_h1);
    cudaGetSymbolAddress((void**)&mid, g_mid);
    cudaGetSymbolAddress((void**)&ffn, g_ffn);

    cudaFuncSetAttribute(mma_gemm<0, 0>, cudaFuncAttributeMaxDynamicSharedMemorySize, GSMEM);
    cudaFuncSetAttribute(mma_gemm<1, 1>, cudaFuncAttributeMaxDynamicSharedMemorySize, GSMEM);
    cudaFuncSetAttribute(mma_gemm<1, 0>, cudaFuncAttributeMaxDynamicSharedMemorySize, GSMEM);
    cudaFuncSetAttribute(emd_mma, cudaFuncAttributeMaxDynamicSharedMemorySize, EM_SMEM);
    cudaFuncSetAttribute(fused_attn, cudaFuncAttributeMaxDynamicSharedMemorySize, FA_SMEM);

    // QKV projections — HMMA bf16x2
    mma_gemm<0, 0><<<dim3(DM / 128, NROW / 128), 256, GSMEM>>>(x, wq, nullptr, Yq, DM, DM);
    mma_gemm<0, 0><<<dim3(DM / 128, NROW / 128), 256, GSMEM>>>(x, wk, nullptr, Yk, DM, DM);
    mma_gemm<0, 0><<<dim3(DM / 128, NROW / 128), 256, GSMEM>>>(x, wv, nullptr, Yv, DM, DM);

    // relative-position logits (live band only) — HMMA
    emd_mma<<<dim3(8, 8, 64), 256, EM_SMEM>>>(Yq, relw, emd);

    // fused scores + skew + batch-softmax + PV — HMMA
    fused_attn<<<dim3(16, 16), 256, FA_SMEM>>>(Yq, Yk, Yv, emd, att);

    // residual + LN1
    add_ln_kernel<<<NROW, 256>>>(x, att, ln1g, ln1b, h1);

    // FFN — HMMA bf16x2
    mma_gemm<1, 1><<<dim3(DFFN / 128, NROW / 128), 256, GSMEM>>>(h1, w1, b1, mid, DFFN, DM);
    mma_gemm<1, 0><<<dim3(DM / 128, NROW / 128), 256, GSMEM>>>(mid, w2, b2, ffn, DM, DFFN);

    // residual + LN2 -> output
    add_ln_kernel<<<NROW, 256>>>(h1, ffn, ln2g, ln2b, out);

    (void)in_sizes; (void)n_in; (void)out_size;
}

// round 10
// speedup vs baseline: 2.4465x; 1.0559x over previous
#include <cuda_runtime.h>
#include <cuda_bf16.h>
#include <math.h>
#include <stdint.h>

// Problem constants
#define SQ   1024
#define NB   4
#define DM   1024
#define NH   16
#define DH   64
#define DFFN 4096
#define NROW 4096          // S*B rows
#define EPSV 1e-5f
#define SS   1048576       // S*S

// ---- scratch (static device globals; no allocation allowed) ----
static __device__ float g_Yq[NROW * DM];
static __device__ float g_Yk[NROW * DM];
static __device__ float g_Yv[NROW * DM];
static __device__ float g_emd[67108864];   // (B,H,S,S) band
static __device__ float g_att[NROW * DM];
static __device__ float g_h1 [NROW * DM];
static __device__ float g_ffn[NROW * DM];
// pre-split bf16 hi/lo operands
static __device__ __nv_bfloat16 g_xh [NROW * DM],  g_xl [NROW * DM];
static __device__ __nv_bfloat16 g_wqh[DM * DM],    g_wql[DM * DM];
static __device__ __nv_bfloat16 g_wkh[DM * DM],    g_wkl[DM * DM];
static __device__ __nv_bfloat16 g_wvh[DM * DM],    g_wvl[DM * DM];
static __device__ __nv_bfloat16 g_w1h[DFFN * DM],  g_w1l[DFFN * DM];
static __device__ __nv_bfloat16 g_w2h[DM * DFFN],  g_w2l[DM * DFFN];
static __device__ __nv_bfloat16 g_h1h[NROW * DM],  g_h1l[NROW * DM];
static __device__ __nv_bfloat16 g_midh[NROW * DFFN], g_midl[NROW * DFFN];

// ============================================================
// common helpers
// ============================================================
__device__ __forceinline__ uint32_t smem_u32(const void* p) {
    uint32_t a;
    asm("{ .reg .u64 t; cvta.to.shared.u64 t, %1; cvt.u32.u64 %0, t; }"
        : "=r"(a) : "l"(p));
    return a;
}

__device__ __forceinline__ void ldsm4(uint32_t addr, uint32_t* r) {
    asm volatile("ldmatrix.sync.aligned.m8n8.x4.shared.b16 {%0,%1,%2,%3}, [%4];"
                 : "=r"(r[0]), "=r"(r[1]), "=r"(r[2]), "=r"(r[3])
                 : "r"(addr));
}

__device__ __forceinline__ void mma16816(float* c, const uint32_t* a, const uint32_t* b) {
    asm volatile(
        "mma.sync.aligned.m16n8k16.row.col.f32.bf16.bf16.f32 "
        "{%0,%1,%2,%3},{%4,%5,%6,%7},{%8,%9},{%0,%1,%2,%3};"
        : "+f"(c[0]), "+f"(c[1]), "+f"(c[2]), "+f"(c[3])
        : "r"(a[0]), "r"(a[1]), "r"(a[2]), "r"(a[3]), "r"(b[0]), "r"(b[1]));
}

// 8 fp32 -> 4 packed bf16x2 hi + 4 lo
__device__ __forceinline__ void cvt_pack8(const float4 v0, const float4 v1,
                                          uint4* hi, uint4* lo) {
    float f[8] = {v0.x, v0.y, v0.z, v0.w, v1.x, v1.y, v1.z, v1.w};
    uint32_t h[4], l[4];
#pragma unroll
    for (int i = 0; i < 4; i++) {
        __nv_bfloat162 hb = __floats2bfloat162_rn(f[2 * i], f[2 * i + 1]);
        float r0 = f[2 * i]     - __bfloat162float(hb.x);
        float r1 = f[2 * i + 1] - __bfloat162float(hb.y);
        __nv_bfloat162 lb = __floats2bfloat162_rn(r0, r1);
        h[i] = *(uint32_t*)&hb;
        l[i] = *(uint32_t*)&lb;
    }
    *hi = make_uint4(h[0], h[1], h[2], h[3]);
    *lo = make_uint4(l[0], l[1], l[2], l[3]);
}

#define CP_ASYNC16(dst, src) \
    asm volatile("cp.async.cg.shared.global [%0], [%1], 16;" \
        :: "r"(dst), "l"(src) : "memory")
#define CP_COMMIT() asm volatile("cp.async.commit_group;" ::: "memory")
#define CP_WAIT2()  asm volatile("cp.async.wait_group 2;" ::: "memory")

// ============================================================
// split fp32 tensor -> bf16 hi + lo
// ============================================================
__global__ __launch_bounds__(256)
void split_kernel(const float4* __restrict__ src, uint2* __restrict__ hi,
                  uint2* __restrict__ lo, int n4) {
    int i = blockIdx.x * blockDim.x + threadIdx.x;
    if (i >= n4) return;
    float4 v = src[i];
    __nv_bfloat162 h0 = __floats2bfloat162_rn(v.x, v.y);
    __nv_bfloat162 h1 = __floats2bfloat162_rn(v.z, v.w);
    __nv_bfloat162 l0 = __floats2bfloat162_rn(v.x - __bfloat162float(h0.x),
                                              v.y - __bfloat162float(h0.y));
    __nv_bfloat162 l1 = __floats2bfloat162_rn(v.z - __bfloat162float(h1.x),
                                              v.w - __bfloat162float(h1.y));
    hi[i] = make_uint2(*(uint32_t*)&h0, *(uint32_t*)&h1);
    lo[i] = make_uint2(*(uint32_t*)&l0, *(uint32_t*)&l1);
}

// ============================================================
// pre-split HMMA GEMM: C = A @ B^T (+bias)(+relu), operands bf16 hi/lo in gmem
// CTA 128x128, BK=64, 3-stage cp.async pipeline, 8 warps (2m x 4n).
// OUT_BF16: write C as bf16 hi/lo instead of fp32.
// ============================================================
#define G2_STRIDE 144                    // bytes per smem row (72 bf16)
#define G2_PART  (128 * G2_STRIDE)       // 18432
#define G2_STAGE (4 * G2_PART)           // 73728
#define G2_SMEM  (3 * G2_STAGE)          // 221184

template<int DO_BIAS, int DO_RELU, int OUT_BF16>
__global__ __launch_bounds__(256, 1)
void mma_gemm2(const __nv_bfloat16* __restrict__ Ah_, const __nv_bfloat16* __restrict__ Al_,
               const __nv_bfloat16* __restrict__ Bh_, const __nv_bfloat16* __restrict__ Bl_,
               const float* __restrict__ bias, float* __restrict__ C,
               __nv_bfloat16* __restrict__ Ch, __nv_bfloat16* __restrict__ Cl,
               int N, int K) {
    extern __shared__ char sm[];
    const int tid = threadIdx.x;
    const int wid = tid >> 5, lane = tid & 31;
    const int m0 = blockIdx.y * 128, n0 = blockIdx.x * 128;
    const int wm = (wid & 1) * 64, wn = (wid >> 1) * 32;

    const __nv_bfloat16* PA0 = Ah_ + (size_t)m0 * K;
    const __nv_bfloat16* PA1 = Al_ + (size_t)m0 * K;
    const __nv_bfloat16* PA2 = Bh_ + (size_t)n0 * K;
    const __nv_bfloat16* PA3 = Bl_ + (size_t)n0 * K;

    const uint32_t sb0 = smem_u32(sm);
    const int NC = K >> 6;

    // per-thread copy mapping: 16 x 16B segments per chunk
    const int c_row[4] = {tid >> 3, (tid + 256) >> 3, (tid + 512) >> 3, (tid + 768) >> 3};
    const int c_k16[4] = {tid & 7, (tid + 256) & 7, (tid + 512) & 7, (tid + 768) & 7};

#define ISSUE_CHUNK(cc, st) do {                                               \
    const int kc_ = (cc) << 6;                                                 \
    const uint32_t bs_ = sb0 + (uint32_t)(st) * G2_STAGE;                      \
    _Pragma("unroll")                                                          \
    for (int q = 0; q < 4; q++) {                                              \
        const int row_ = c_row[q], k16_ = c_k16[q];                            \
        const uint32_t d_ = bs_ + row_ * G2_STRIDE + k16_ * 16;                \
        const size_t  o_ = (size_t)row_ * K + kc_ + k16_ * 8;                  \
        CP_ASYNC16(d_,                (const void*)(PA0 + o_));                \
        CP_ASYNC16(d_ +     G2_PART,  (const void*)(PA1 + o_));                \
        CP_ASYNC16(d_ + 2 * G2_PART,  (const void*)(PA2 + o_));                \
        CP_ASYNC16(d_ + 3 * G2_PART,  (const void*)(PA3 + o_));                \
    }                                                                          \
} while (0)

    ISSUE_CHUNK(0, 0); CP_COMMIT();
    ISSUE_CHUNK(1, 1); CP_COMMIT();
    ISSUE_CHUNK(2, 2); CP_COMMIT();

    float acc[4][4][4];
#pragma unroll
    for (int i = 0; i < 4; i++)
#pragma unroll
        for (int j = 0; j < 4; j++)
#pragma unroll
            for (int r = 0; r < 4; r++) acc[i][j][r] = 0.f;

    const uint32_t a_off = (uint32_t)((wm + (lane & 15)) * G2_STRIDE)
                         + ((lane >> 4) & 1) * 16;
    const uint32_t b_off = (uint32_t)((wn + (lane & 7) + ((lane >> 4) & 1) * 8) * G2_STRIDE)
                         + ((lane >> 3) & 1) * 16;

    for (int c = 0; c < NC; c++) {
        CP_WAIT2();
        __syncthreads();
        const int st = c % 3;
        const uint32_t aA = sb0 + st * G2_STAGE + a_off;
        const uint32_t aB = sb0 + st * G2_STAGE + 2 * G2_PART + b_off;
#pragma unroll
        for (int ks = 0; ks < 4; ks++) {
            uint32_t Ah[4][4], Al[4][4], Bh[4][2], Bl[4][2];
#pragma unroll
            for (int mt = 0; mt < 4; mt++)
                ldsm4(aA + mt * (16 * G2_STRIDE) + ks * 32, Ah[mt]);
#pragma unroll
            for (int mt = 0; mt < 4; mt++)
                ldsm4(aA + G2_PART + mt * (16 * G2_STRIDE) + ks * 32, Al[mt]);
#pragma unroll
            for (int bt = 0; bt < 2; bt++) {
                uint32_t r[4];
                ldsm4(aB + bt * (16 * G2_STRIDE) + ks * 32, r);
                Bh[2 * bt][0] = r[0]; Bh[2 * bt][1] = r[1];
                Bh[2 * bt + 1][0] = r[2]; Bh[2 * bt + 1][1] = r[3];
            }
#pragma unroll
            for (int bt = 0; bt < 2; bt++) {
                uint32_t r[4];
                ldsm4(aB + G2_PART + bt * (16 * G2_STRIDE) + ks * 32, r);
                Bl[2 * bt][0] = r[0]; Bl[2 * bt][1] = r[1];
                Bl[2 * bt + 1][0] = r[2]; Bl[2 * bt + 1][1] = r[3];
            }
#pragma unroll
            for (int mt = 0; mt < 4; mt++)
#pragma unroll
                for (int nt = 0; nt < 4; nt++)
                    mma16816(acc[mt][nt], Ah[mt], Bh[nt]);
#pragma unroll
            for (int mt = 0; mt < 4; mt++)
#pragma unroll
                for (int nt = 0; nt < 4; nt++)
                    mma16816(acc[mt][nt], Ah[mt], Bl[nt]);
#pragma unroll
            for (int mt = 0; mt < 4; mt++)
#pragma unroll
                for (int nt = 0; nt < 4; nt++)
                    mma16816(acc[mt][nt], Al[mt], Bh[nt]);
        }
        __syncthreads();
        if (c + 3 < NC) ISSUE_CHUNK(c + 3, st);
        CP_COMMIT();
    }
#undef ISSUE_CHUNK

    const int er = lane >> 2, ec = (lane & 3) * 2;
#pragma unroll
    for (int mt = 0; mt < 4; mt++) {
        const int row0 = m0 + wm + mt * 16 + er;
#pragma unroll
        for (int nt = 0; nt < 4; nt++) {
            const int col = n0 + wn + nt * 8 + ec;
            float2 bv = make_float2(0.f, 0.f);
            if (DO_BIAS) bv = *(const float2*)(bias + col);
            float2 o0, o1;
            o0.x = acc[mt][nt][0] + bv.x; o0.y = acc[mt][nt][1] + bv.y;
            o1.x = acc[mt][nt][2] + bv.x; o1.y = acc[mt][nt][3] + bv.y;
            if (DO_RELU) {
                o0.x = fmaxf(o0.x, 0.f); o0.y = fmaxf(o0.y, 0.f);
                o1.x = fmaxf(o1.x, 0.f); o1.y = fmaxf(o1.y, 0.f);
            }
            if (OUT_BF16) {
#pragma unroll
                for (int half = 0; half < 2; half++) {
                    float2 o = half ? o1 : o0;
                    const size_t off = (size_t)(row0 + half * 8) * N + col;
                    __nv_bfloat162 hb = __floats2bfloat162_rn(o.x, o.y);
                    __nv_bfloat162 lb = __floats2bfloat162_rn(o.x - __bfloat162float(hb.x),
                                                              o.y - __bfloat162float(hb.y));
                    *(uint32_t*)(Ch + off) = *(uint32_t*)&hb;
                    *(uint32_t*)(Cl + off) = *(uint32_t*)&lb;
                }
            } else {
                *(float2*)(C + (size_t)row0 * N + col)       = o0;
                *(float2*)(C + (size_t)(row0 + 8) * N + col) = o1;
            }
        }
    }
}

// ============================================================
// emd (HMMA): emd[b,h,s,j] = sum_i Q[b,h,s,i]*relw[b,h,i,j]
// 128x128 tiles, K=64, bf16x2 split. Only band s+j>=1023 is live.
// ============================================================
#define EM_STRIDE 72
#define EM_PART (128 * EM_STRIDE * 2)   // 18432
#define EM_SCR  (4 * EM_PART)
#define EM_SMEM (4 * EM_PART + 64 * 132 * 4)   // 107520

__global__ __launch_bounds__(256, 2)
void emd_mma(const float* __restrict__ Yq, const float* __restrict__ relw,
             float* __restrict__ emd) {
    const int bh = blockIdx.z, b = bh >> 4, h = bh & 15;
    const int s0 = blockIdx.y * 128, j0 = blockIdx.x * 128;
    if (s0 + j0 < 769) return;
    extern __shared__ char sm[];
    float* scr = (float*)(sm + EM_SCR);
    const int tid = threadIdx.x;
    const int wid = tid >> 5, lane = tid & 31;
    const int wm = (wid & 1) * 64, wn = (wid >> 1) * 32;

    {
        const int lr = tid >> 1, lk = (tid & 1) * 32;
        const float* qp = Yq + (size_t)(b * SQ + s0 + lr) * DM + h * DH + lk;
        const uint32_t so = (uint32_t)(lr * EM_STRIDE + lk) * 2;
#pragma unroll
        for (int i = 0; i < 4; i++) {
            float4 v0 = *(const float4*)(qp + i * 8);
            float4 v1 = *(const float4*)(qp + i * 8 + 4);
            uint4 hh, ll;
            cvt_pack8(v0, v1, &hh, &ll);
            *(uint4*)(sm + so + i * 16)           = hh;
            *(uint4*)(sm + EM_PART + so + i * 16) = ll;
        }
    }
#pragma unroll
    for (int it = 0; it < 8; it++) {
        int f = tid + it * 256;
        int i = f >> 5, jf = (f & 31) * 4;
        float4 v = *(const float4*)(relw + ((size_t)bh * DH + i) * SQ + j0 + jf);
        *(float4*)(scr + i * 132 + jf) = v;
    }
    __syncthreads();
#pragma unroll
    for (int it = 0; it < 8; it++) {
        int u = tid + it * 256;
        int j = u & 127, i4 = (u >> 7) * 4;
        float f0 = scr[(i4 + 0) * 132 + j];
        float f1 = scr[(i4 + 1) * 132 + j];
        float f2 = scr[(i4 + 2) * 132 + j];
        float f3 = scr[(i4 + 3) * 132 + j];
        __nv_bfloat162 h01 = __floats2bfloat162_rn(f0, f1);
        __nv_bfloat162 h23 = __floats2bfloat162_rn(f2, f3);
        __nv_bfloat162 l01 = __floats2bfloat162_rn(f0 - __bfloat162float(h01.x),
                                                   f1 - __bfloat162float(h01.y));
        __nv_bfloat162 l23 = __floats2bfloat162_rn(f2 - __bfloat162float(h23.x),
                                                   f3 - __bfloat162float(h23.y));
        const uint32_t o = (uint32_t)(j * 144 + i4 * 2);
        *(uint2*)(sm + 2 * EM_PART + o) = make_uint2(*(uint32_t*)&h01, *(uint32_t*)&h23);
        *(uint2*)(sm + 3 * EM_PART + o) = make_uint2(*(uint32_t*)&l01, *(uint32_t*)&l23);
    }
    __syncthreads();

    float acc[4][4][4];
#pragma unroll
    for (int i = 0; i < 4; i++)
#pragma unroll
        for (int j = 0; j < 4; j++)
#pragma unroll
            for (int r = 0; r < 4; r++) acc[i][j][r] = 0.f;

    const uint32_t sb = smem_u32(sm);
    const uint32_t a_off = (uint32_t)((wm + (lane & 15)) * EM_STRIDE) * 2
                         + ((lane >> 4) & 1) * 16;
    const uint32_t b_off = (uint32_t)((wn + (lane & 7) + ((lane >> 4) & 1) * 8) * EM_STRIDE) * 2
                         + ((lane >> 3) & 1) * 16;

#pragma unroll
    for (int ks = 0; ks < 4; ks++) {
        uint32_t AhF[4][4], AlF[4][4], BhF[4][2], BlF[4][2];
#pragma unroll
        for (int mt = 0; mt < 4; mt++)
            ldsm4(sb + a_off + mt * 2304 + ks * 32, AhF[mt]);
#pragma unroll
        for (int mt = 0; mt < 4; mt++)
            ldsm4(sb + EM_PART + a_off + mt * 2304 + ks * 32, AlF[mt]);
#pragma unroll
        for (int bt = 0; bt < 2; bt++) {
            uint32_t r[4];
            ldsm4(sb + 2 * EM_PART + b_off + bt * 2304 + ks * 32, r);
            BhF[2 * bt][0] = r[0]; BhF[2 * bt][1] = r[1];
            BhF[2 * bt + 1][0] = r[2]; BhF[2 * bt + 1][1] = r[3];
        }
#pragma unroll
        for (int bt = 0; bt < 2; bt++) {
            uint32_t r[4];
            ldsm4(sb + 3 * EM_PART + b_off + bt * 2304 + ks * 32, r);
            BlF[2 * bt][0] = r[0]; BlF[2 * bt][1] = r[1];
            BlF[2 * bt + 1][0] = r[2]; BlF[2 * bt + 1][1] = r[3];
        }
#pragma unroll
        for (int mt = 0; mt < 4; mt++)
#pragma unroll
            for (int nt = 0; nt < 4; nt++)
                mma16816(acc[mt][nt], AhF[mt], BhF[nt]);
#pragma unroll
        for (int mt = 0; mt < 4; mt++)
#pragma unroll
            for (int nt = 0; nt < 4; nt++)
                mma16816(acc[mt][nt], AhF[mt], BlF[nt]);
#pragma unroll
        for (int mt = 0; mt < 4; mt++)
#pragma unroll
            for (int nt = 0; nt < 4; nt++)
                mma16816(acc[mt][nt], AlF[mt], BhF[nt]);
    }

    const int er = lane >> 2, ec = (lane & 3) * 2;
#pragma unroll
    for (int mt = 0; mt < 4; mt++) {
#pragma unroll
        for (int nt = 0; nt < 4; nt++) {
            const int col = j0 + wn + nt * 8 + ec;
#pragma unroll
            for (int half = 0; half < 2; half++) {
                const int sg = s0 + wm + mt * 16 + er + half * 8;
                *(float2*)(emd + (size_t)bh * SS + (size_t)sg * SQ + col) =
                    make_float2(acc[mt][nt][2 * half], acc[mt][nt][2 * half + 1]);
            }
        }
    }
}

// ============================================================
// fused attention: scores(QK^T*0.125 + skew) -> softmax over batch -> PV
// ============================================================
#define FA_B 18432
#define FA_SC_OFF 73728
#define FA_P_OFF  147456
#define FA_SMEM   221184

__global__ __launch_bounds__(256, 1)
void fused_attn(const float* __restrict__ Yq, const float* __restrict__ Yk,
                const float* __restrict__ Yv, const float* __restrict__ emd,
                float* __restrict__ out) {
    extern __shared__ char sm[];
    char* smKV = sm;
    char* smSC = sm + FA_SC_OFF;
    char* smP  = sm + FA_P_OFF;
    const int tid = threadIdx.x;
    const int wid = tid >> 5, lane = tid & 31;
    const int s0 = blockIdx.x * 64;
    const int h  = blockIdx.y;
    const int bq = wid >> 1;
    const int wm = (wid & 1) * 32;
    const int er = lane >> 2, ec = (lane & 3) * 2;

    const uint32_t sb = smem_u32(sm);
    const int lr = tid >> 1;
    const int lk = (tid & 1) * 32;

#pragma unroll
    for (int it = 0; it < 2; it++) {
        int row = lr + it * 128;
        int b = row >> 6, r = row & 63;
        const float* p = Yq + (size_t)(b * SQ + s0 + r) * DM + h * DH + lk;
        char* dst = smKV + b * FA_B + r * 144 + lk * 2;
#pragma unroll
        for (int i = 0; i < 2; i++) {
            float4 v0 = *(const float4*)(p + i * 16);
            float4 v1 = *(const float4*)(p + i * 16 + 4);
            float4 v2 = *(const float4*)(p + i * 16 + 8);
            float4 v3 = *(const float4*)(p + i * 16 + 12);
            uint4 h0, l0, h1, l1;
            cvt_pack8(v0, v1, &h0, &l0);
            cvt_pack8(v2, v3, &h1, &l1);
            *(uint4*)(dst + i * 32)              = h0;
            *(uint4*)(dst + i * 32 + 16)         = h1;
            *(uint4*)(dst + 9216 + i * 32)       = l0;
            *(uint4*)(dst + 9216 + i * 32 + 16)  = l1;
        }
    }
    __syncthreads();

    uint32_t Qh[2][4][4], Ql[2][4][4];
    {
        const uint32_t aQ = sb + (uint32_t)bq * FA_B + (wm + (lane & 15)) * 144
                          + ((lane >> 4) & 1) * 16;
#pragma unroll
        for (int mt = 0; mt < 2; mt++)
#pragma unroll
            for (int ks = 0; ks < 4; ks++) {
                ldsm4(aQ + mt * 2304 + ks * 32, Qh[mt][ks]);
                ldsm4(aQ + 9216 + mt * 2304 + ks * 32, Ql[mt][ks]);
            }
    }

    float oacc[2][8][4];
#pragma unroll
    for (int i = 0; i < 2; i++)
#pragma unroll
        for (int j = 0; j < 8; j++)
#pragma unroll
            for (int r = 0; r < 4; r++) oacc[i][j][r] = 0.f;

    const uint32_t kvB = sb + (uint32_t)bq * FA_B
                       + ((lane & 7) + ((lane >> 4) & 1) * 8) * 144
                       + ((lane >> 3) & 1) * 16;
    const uint32_t aP = sb + FA_P_OFF + (uint32_t)bq * FA_B
                      + (wm + (lane & 15)) * 144 + ((lane >> 4) & 1) * 16;
    const size_t ebase = (size_t)(bq * NH + h) * SS;

    for (int t0 = 0; t0 < SQ; t0 += 64) {
        __syncthreads();

#pragma unroll
        for (int it = 0; it < 2; it++) {
            int row = lr + it * 128;
            int b = row >> 6, r = row & 63;
            const float* p = Yk + (size_t)(b * SQ + t0 + r) * DM + h * DH + lk;
            char* dst = smKV + b * FA_B + r * 144 + lk * 2;
#pragma unroll
            for (int i = 0; i < 2; i++) {
                float4 v0 = *(const float4*)(p + i * 16);
                float4 v1 = *(const float4*)(p + i * 16 + 4);
                float4 v2 = *(const float4*)(p + i * 16 + 8);
                float4 v3 = *(const float4*)(p + i * 16 + 12);
                uint4 h0, l0, h1, l1;
                cvt_pack8(v0, v1, &h0, &l0);
                cvt_pack8(v2, v3, &h1, &l1);
                *(uint4*)(dst + i * 32)              = h0;
                *(uint4*)(dst + i * 32 + 16)         = h1;
                *(uint4*)(dst + 9216 + i * 32)       = l0;
                *(uint4*)(dst + 9216 + i * 32 + 16)  = l1;
            }
        }
        __syncthreads();

        float qk[2][8][4];
#pragma unroll
        for (int i = 0; i < 2; i++)
#pragma unroll
            for (int j = 0; j < 8; j++)
#pragma unroll
                for (int r = 0; r < 4; r++) qk[i][j][r] = 0.f;
#pragma unroll
        for (int ks = 0; ks < 4; ks++) {
            uint32_t Bh[8][2], Bl[8][2];
#pragma unroll
            for (int bt = 0; bt < 4; bt++) {
                uint32_t r[4];
                ldsm4(kvB + bt * 2304 + ks * 32, r);
                Bh[2 * bt][0] = r[0]; Bh[2 * bt][1] = r[1];
                Bh[2 * bt + 1][0] = r[2]; Bh[2 * bt + 1][1] = r[3];
            }
#pragma unroll
            for (int bt = 0; bt < 4; bt++) {
                uint32_t r[4];
                ldsm4(kvB + 9216 + bt * 2304 + ks * 32, r);
                Bl[2 * bt][0] = r[0]; Bl[2 * bt][1] = r[1];
                Bl[2 * bt + 1][0] = r[2]; Bl[2 * bt + 1][1] = r[3];
            }
#pragma unroll
            for (int mt = 0; mt < 2; mt++)
#pragma unroll
                for (int nt = 0; nt < 8; nt++)
                    mma16816(qk[mt][nt], Qh[mt][ks], Bh[nt]);
#pragma unroll
            for (int mt = 0; mt < 2; mt++)
#pragma unroll
                for (int nt = 0; nt < 8; nt++)
                    mma16816(qk[mt][nt], Qh[mt][ks], Bl[nt]);
#pragma unroll
            for (int mt = 0; mt < 2; mt++)
#pragma unroll
                for (int nt = 0; nt < 8; nt++)
                    mma16816(qk[mt][nt], Ql[mt][ks], Bh[nt]);
        }

#pragma unroll
        for (int mt = 0; mt < 2; mt++) {
#pragma unroll
            for (int nt = 0; nt < 8; nt++) {
                const int tg = nt * 8 + ec;
                const int tgl = t0 + tg;
#pragma unroll
                for (int half = 0; half < 2; half++) {
                    const int sg = wm + mt * 16 + er + half * 8;
                    const int sgl = s0 + sg;
                    float v0 = 0.125f * qk[mt][nt][2 * half];
                    float v1 = 0.125f * qk[mt][nt][2 * half + 1];
                    if (tgl <= sgl)
                        v0 += emd[ebase + (size_t)sgl * SQ + 1023 + tgl - sgl];
                    if (tgl + 1 <= sgl)
                        v1 += emd[ebase + (size_t)sgl * SQ + 1024 + tgl - sgl];
                    *(float2*)(smSC + bq * FA_B + sg * 288 + tg * 4) = make_float2(v0, v1);
                }
            }
        }
        __syncthreads();

#pragma unroll
        for (int i = 0; i < 8; i++) {
            const int e = tid + i * 256;
            const int s = e >> 5, t2 = (e & 31) * 2;
            float2 v[4];
#pragma unroll
            for (int b = 0; b < 4; b++)
                v[b] = *(const float2*)(smSC + b * FA_B + s * 288 + t2 * 4);
            float m0 = fmaxf(fmaxf(v[0].x, v[1].x), fmaxf(v[2].x, v[3].x));
            float m1 = fmaxf(fmaxf(v[0].y, v[1].y), fmaxf(v[2].y, v[3].y));
            float e0[4], e1[4];
            float sum0 = 0.f, sum1 = 0.f;
#pragma unroll
            for (int b = 0; b < 4; b++) {
                e0[b] = __expf(v[b].x - m0); sum0 += e0[b];
                e1[b] = __expf(v[b].y - m1); sum1 += e1[b];
            }
            const float i0 = 1.f / sum0, i1 = 1.f / sum1;
#pragma unroll
            for (int b = 0; b < 4; b++) {
                float p0 = e0[b] * i0, p1 = e1[b] * i1;
                __nv_bfloat162 hb = __floats2bfloat162_rn(p0, p1);
                float r0 = p0 - __bfloat162float(hb.x);
                float r1 = p1 - __bfloat162float(hb.y);
                __nv_bfloat162 lb = __floats2bfloat162_rn(r0, r1);
                *(uint32_t*)(smP + b * FA_B + s * 144 + t2 * 2)        = *(uint32_t*)&hb;
                *(uint32_t*)(smP + b * FA_B + 9216 + s * 144 + t2 * 2) = *(uint32_t*)&lb;
            }
        }
#pragma unroll
        for (int it = 0; it < 4; it++) {
            const int f = tid + it * 256;
            const int d = f & 63;
            const int t4 = (f >> 6) * 4;
#pragma unroll
            for (int b = 0; b < 4; b++) {
                const float* vp = Yv + (size_t)(b * SQ + t0 + t4) * DM + h * DH + d;
                float v0 = vp[0];
                float v1 = vp[DM];
                float v2 = vp[2 * DM];
                float v3 = vp[3 * DM];
                __nv_bfloat162 h01 = __floats2bfloat162_rn(v0, v1);
                __nv_bfloat162 h23 = __floats2bfloat162_rn(v2, v3);
                __nv_bfloat162 l01 = __floats2bfloat162_rn(v0 - __bfloat162float(h01.x),
                                                           v1 - __bfloat162float(h01.y));
                __nv_bfloat162 l23 = __floats2bfloat162_rn(v2 - __bfloat162float(h23.x),
                                                           v3 - __bfloat162float(h23.y));
                char* vb = smKV + b * FA_B;
                const uint32_t vo = (uint32_t)(d * 144 + t4 * 2);
                *(uint2*)(vb + vo)        = make_uint2(*(uint32_t*)&h01, *(uint32_t*)&h23);
                *(uint2*)(vb + 9216 + vo) = make_uint2(*(uint32_t*)&l01, *(uint32_t*)&l23);
            }
        }
        __syncthreads();

#pragma unroll
        for (int ks = 0; ks < 4; ks++) {
            uint32_t Ph[2][4], Pl[2][4], Vh[8][2], Vl[8][2];
#pragma unroll
            for (int mt = 0; mt < 2; mt++) {
                ldsm4(aP + mt * 2304 + ks * 32, Ph[mt]);
                ldsm4(aP + 9216 + mt * 2304 + ks * 32, Pl[mt]);
            }
#pragma unroll
            for (int bt = 0; bt < 4; bt++) {
                uint32_t r[4];
                ldsm4(kvB + bt * 2304 + ks * 32, r);
                Vh[2 * bt][0] = r[0]; Vh[2 * bt][1] = r[1];
                Vh[2 * bt + 1][0] = r[2]; Vh[2 * bt + 1][1] = r[3];
            }
#pragma unroll
            for (int bt = 0; bt < 4; bt++) {
                uint32_t r[4];
                ldsm4(kvB + 9216 + bt * 2304 + ks * 32, r);
                Vl[2 * bt][0] = r[0]; Vl[2 * bt][1] = r[1];
                Vl[2 * bt + 1][0] = r[2]; Vl[2 * bt + 1][1] = r[3];
            }
#pragma unroll
            for (int mt = 0; mt < 2; mt++)
#pragma unroll
                for (int nt = 0; nt < 8; nt++)
                    mma16816(oacc[mt][nt], Ph[mt], Vh[nt]);
#pragma unroll
            for (int mt = 0; mt < 2; mt++)
#pragma unroll
                for (int nt = 0; nt < 8; nt++)
                    mma16816(oacc[mt][nt], Ph[mt], Vl[nt]);
#pragma unroll
            for (int mt = 0; mt < 2; mt++)
#pragma unroll
                for (int nt = 0; nt < 8; nt++)
                    mma16816(oacc[mt][nt], Pl[mt], Vh[nt]);
        }
    }

#pragma unroll
    for (int mt = 0; mt < 2; mt++) {
        const int row = s0 + wm + mt * 16 + er;
        float* op = out + ((size_t)(bq * NH + h) * SQ + row) * DH;
#pragma unroll
        for (int nt = 0; nt < 8; nt++) {
            const int col = nt * 8 + ec;
            *(float2*)(op + col)          = make_float2(oacc[mt][nt][0], oacc[mt][nt][1]);
            *(float2*)(op + 8 * DH + col) = make_float2(oacc[mt][nt][2], oacc[mt][nt][3]);
        }
    }
}

// ============================================================
// residual + LayerNorm (optionally emitting bf16 hi/lo split)
// ============================================================
__device__ __forceinline__ float block_sum256(float v, float* red) {
#pragma unroll
    for (int o = 16; o > 0; o >>= 1) v += __shfl_xor_sync(0xffffffffu, v, o);
    int t = threadIdx.x;
    if ((t & 31) == 0) red[t >> 5] = v;
    __syncthreads();
    if (t == 0) {
        float s = 0.f;
#pragma unroll
        for (int i = 0; i < 8; i++) s += red[i];
        red[0] = s;
    }
    __syncthreads();
    float res = red[0];
    __syncthreads();
    return res;
}

template<int SPLIT>
__global__ __launch_bounds__(256)
void add_ln_kernel(const float* __restrict__ xa, const float* __restrict__ xb,
                   const float* __restrict__ g, const float* __restrict__ bb,
                   float* __restrict__ out,
                   __nv_bfloat16* __restrict__ oh, __nv_bfloat16* __restrict__ ol) {
    const int row = blockIdx.x;
    const float* pa = xa + (size_t)row * DM;
    const float* pb = xb + (size_t)row * DM;
    __shared__ float red[8];
    const int t = threadIdx.x;

    float loc[4];
    float s = 0.f;
#pragma unroll
    for (int u = 0; u < 4; u++) {
        int i = t + u * 256;
        float v = pa[i] + pb[i];
        loc[u] = v;
        s += v;
    }
    float mean = block_sum256(s, red) * (1.f / 1024.f);

    float vs = 0.f;
#pragma unroll
    for (int u = 0; u < 4; u++) {
        float d = loc[u] - mean;
        vs += d * d;
    }
    float var = block_sum256(vs, red) * (1.f / 1024.f);
    float inv = rsqrtf(var + EPSV);

#pragma unroll
    for (int u = 0; u < 4; u++) {
        int i = t + u * 256;
        float o = (loc[u] - mean) * inv * g[i] + bb[i];
        out[(size_t)row * DM + i] = o;
        if (SPLIT) {
            __nv_bfloat16 hb = __float2bfloat16_rn(o);
            __nv_bfloat16 lb = __float2bfloat16_rn(o - __bfloat162float(hb));
            oh[(size_t)row * DM + i] = hb;
            ol[(size_t)row * DM + i] = lb;
        }
    }
}

// ============================================================
extern "C" void kernel_launch(void* const* d_in, const int* in_sizes, int n_in,
                              void* d_out, int out_size) {
    const float* x    = (const float*)d_in[0];
    const float* wq   = (const float*)d_in[1];
    const float* wk   = (const float*)d_in[2];
    const float* wv   = (const float*)d_in[3];
    const float* relw = (const float*)d_in[4];
    const float* ln1g = (const float*)d_in[5];
    const float* ln1b = (const float*)d_in[6];
    const float* ln2g = (const float*)d_in[7];
    const float* ln2b = (const float*)d_in[8];
    const float* w1   = (const float*)d_in[9];
    const float* b1   = (const float*)d_in[10];
    const float* w2   = (const float*)d_in[11];
    const float* b2   = (const float*)d_in[12];
    float* out = (float*)d_out;

    float *Yq, *Yk, *Yv, *emd, *att, *h1, *ffn;
    __nv_bfloat16 *xh, *xl, *wqh, *wql, *wkh, *wkl, *wvh, *wvl;
    __nv_bfloat16 *w1h, *w1l, *w2h, *w2l, *h1h, *h1l, *midh, *midl;
    cudaGetSymbolAddress((void**)&Yq,  g_Yq);
    cudaGetSymbolAddress((void**)&Yk,  g_Yk);
    cudaGetSymbolAddress((void**)&Yv,  g_Yv);
    cudaGetSymbolAddress((void**)&emd, g_emd);
    cudaGetSymbolAddress((void**)&att, g_att);
    cudaGetSymbolAddress((void**)&h1,  g_h1);
    cudaGetSymbolAddress((void**)&ffn, g_ffn);
    cudaGetSymbolAddress((void**)&xh,  g_xh);   cudaGetSymbolAddress((void**)&xl,  g_xl);
    cudaGetSymbolAddress((void**)&wqh, g_wqh);  cudaGetSymbolAddress((void**)&wql, g_wql);
    cudaGetSymbolAddress((void**)&wkh, g_wkh);  cudaGetSymbolAddress((void**)&wkl, g_wkl);
    cudaGetSymbolAddress((void**)&wvh, g_wvh);  cudaGetSymbolAddress((void**)&wvl, g_wvl);
    cudaGetSymbolAddress((void**)&w1h, g_w1h);  cudaGetSymbolAddress((void**)&w1l, g_w1l);
    cudaGetSymbolAddress((void**)&w2h, g_w2h);  cudaGetSymbolAddress((void**)&w2l, g_w2l);
    cudaGetSymbolAddress((void**)&h1h, g_h1h);  cudaGetSymbolAddress((void**)&h1l, g_h1l);
    cudaGetSymbolAddress((void**)&midh, g_midh); cudaGetSymbolAddress((void**)&midl, g_midl);

    cudaFuncSetAttribute(mma_gemm2<0, 0, 0>, cudaFuncAttributeMaxDynamicSharedMemorySize, G2_SMEM);
    cudaFuncSetAttribute(mma_gemm2<1, 1, 1>, cudaFuncAttributeMaxDynamicSharedMemorySize, G2_SMEM);
    cudaFuncSetAttribute(mma_gemm2<1, 0, 0>, cudaFuncAttributeMaxDynamicSharedMemorySize, G2_SMEM);
    cudaFuncSetAttribute(emd_mma, cudaFuncAttributeMaxDynamicSharedMemorySize, EM_SMEM);
    cudaFuncSetAttribute(fused_attn, cudaFuncAttributeMaxDynamicSharedMemorySize, FA_SMEM);

    // ---- split pre-pass: x + all weights ----
    split_kernel<<<(NROW * DM / 4 + 255) / 256, 256>>>((const float4*)x, (uint2*)xh, (uint2*)xl, NROW * DM / 4);
    split_kernel<<<(DM * DM / 4 + 255) / 256, 256>>>((const float4*)wq, (uint2*)wqh, (uint2*)wql, DM * DM / 4);
    split_kernel<<<(DM * DM / 4 + 255) / 256, 256>>>((const float4*)wk, (uint2*)wkh, (uint2*)wkl, DM * DM / 4);
    split_kernel<<<(DM * DM / 4 + 255) / 256, 256>>>((const float4*)wv, (uint2*)wvh, (uint2*)wvl, DM * DM / 4);
    split_kernel<<<(DFFN * DM / 4 + 255) / 256, 256>>>((const float4*)w1, (uint2*)w1h, (uint2*)w1l, DFFN * DM / 4);
    split_kernel<<<(DM * DFFN / 4 + 255) / 256, 256>>>((const float4*)w2, (uint2*)w2h, (uint2*)w2l, DM * DFFN / 4);

    // ---- QKV projections (cp.async HMMA) ----
    mma_gemm2<0, 0, 0><<<dim3(DM / 128, NROW / 128), 256, G2_SMEM>>>(
        xh, xl, wqh, wql, nullptr, Yq, nullptr, nullptr, DM, DM);
    mma_gemm2<0, 0, 0><<<dim3(DM / 128, NROW / 128), 256, G2_SMEM>>>(
        xh, xl, wkh, wkl, nullptr, Yk, nullptr, nullptr, DM, DM);
    mma_gemm2<0, 0, 0><<<dim3(DM / 128, NROW / 128), 256, G2_SMEM>>>(
        xh, xl, wvh, wvl, nullptr, Yv, nullptr, nullptr, DM, DM);

    // ---- relative-position logits (live band only) ----
    emd_mma<<<dim3(8, 8, 64), 256, EM_SMEM>>>(Yq, relw, emd);

    // ---- fused scores + skew + batch-softmax + PV ----
    fused_attn<<<dim3(16, 16), 256, FA_SMEM>>>(Yq, Yk, Yv, emd, att);

    // ---- residual + LN1 (emit fp32 + bf16 split) ----
    add_ln_kernel<1><<<NROW, 256>>>(x, att, ln1g, ln1b, h1, h1h, h1l);

    // ---- FFN1: h1 @ w1^T + b1, relu -> mid (bf16 hi/lo only) ----
    mma_gemm2<1, 1, 1><<<dim3(DFFN / 128, NROW / 128), 256, G2_SMEM>>>(
        h1h, h1l, w1h, w1l, b1, nullptr, midh, midl, DFFN, DM);

    // ---- FFN2: mid @ w2^T + b2 -> ffn (fp32) ----
    mma_gemm2<1, 0, 0><<<dim3(DM / 128, NROW / 128), 256, G2_SMEM>>>(
        midh, midl, w2h, w2l, b2, ffn, nullptr, nullptr, DM, DFFN);

    // ---- residual + LN2 -> output ----
    add_ln_kernel<0><<<NROW, 256>>>(h1, ffn, ln2g, ln2b, out, nullptr, nullptr);

    (void)in_sizes; (void)n_in; (void)out_size;
}

// round 16
// speedup vs baseline: 2.4729x; 1.0108x over previous
#include <cuda_runtime.h>
#include <cuda_bf16.h>
#include <math.h>
#include <stdint.h>

// Problem constants
#define SQ   1024
#define NB   4
#define DM   1024
#define NH   16
#define DH   64
#define DFFN 4096
#define NROW 4096          // S*B rows
#define EPSV 1e-5f
#define SS   1048576       // S*S

// ---- scratch (static device globals; no allocation allowed) ----
static __device__ float g_Yq[NROW * DM];
static __device__ float g_Yk[NROW * DM];
static __device__ float g_Yv[NROW * DM];
static __device__ float g_emd[67108864];   // (B,H,S,S) band
static __device__ float g_att[NROW * DM];
static __device__ float g_h1 [NROW * DM];
static __device__ float g_ffn[NROW * DM];
// pre-split bf16 hi/lo operands
static __device__ __nv_bfloat16 g_xh [NROW * DM],  g_xl [NROW * DM];
static __device__ __nv_bfloat16 g_wqh[DM * DM],    g_wql[DM * DM];
static __device__ __nv_bfloat16 g_wkh[DM * DM],    g_wkl[DM * DM];
static __device__ __nv_bfloat16 g_wvh[DM * DM],    g_wvl[DM * DM];
static __device__ __nv_bfloat16 g_w1h[DFFN * DM],  g_w1l[DFFN * DM];
static __device__ __nv_bfloat16 g_w2h[DM * DFFN],  g_w2l[DM * DFFN];
static __device__ __nv_bfloat16 g_h1h[NROW * DM],  g_h1l[NROW * DM];
static __device__ __nv_bfloat16 g_midh[NROW * DFFN], g_midl[NROW * DFFN];

// ============================================================
// common helpers
// ============================================================
__device__ __forceinline__ uint32_t smem_u32(const void* p) {
    uint32_t a;
    asm("{ .reg .u64 t; cvta.to.shared.u64 t, %1; cvt.u32.u64 %0, t; }"
        : "=r"(a) : "l"(p));
    return a;
}

__device__ __forceinline__ void ldsm4(uint32_t addr, uint32_t* r) {
    asm volatile("ldmatrix.sync.aligned.m8n8.x4.shared.b16 {%0,%1,%2,%3}, [%4];"
                 : "=r"(r[0]), "=r"(r[1]), "=r"(r[2]), "=r"(r[3])
                 : "r"(addr));
}

__device__ __forceinline__ void mma16816(float* c, const uint32_t* a, const uint32_t* b) {
    asm volatile(
        "mma.sync.aligned.m16n8k16.row.col.f32.bf16.bf16.f32 "
        "{%0,%1,%2,%3},{%4,%5,%6,%7},{%8,%9},{%0,%1,%2,%3};"
        : "+f"(c[0]), "+f"(c[1]), "+f"(c[2]), "+f"(c[3])
        : "r"(a[0]), "r"(a[1]), "r"(a[2]), "r"(a[3]), "r"(b[0]), "r"(b[1]));
}

// 8 fp32 -> 4 packed bf16x2 hi + 4 lo
__device__ __forceinline__ void cvt_pack8(const float4 v0, const float4 v1,
                                          uint4* hi, uint4* lo) {
    float f[8] = {v0.x, v0.y, v0.z, v0.w, v1.x, v1.y, v1.z, v1.w};
    uint32_t h[4], l[4];
#pragma unroll
    for (int i = 0; i < 4; i++) {
        __nv_bfloat162 hb = __floats2bfloat162_rn(f[2 * i], f[2 * i + 1]);
        float r0 = f[2 * i]     - __bfloat162float(hb.x);
        float r1 = f[2 * i + 1] - __bfloat162float(hb.y);
        __nv_bfloat162 lb = __floats2bfloat162_rn(r0, r1);
        h[i] = *(uint32_t*)&hb;
        l[i] = *(uint32_t*)&lb;
    }
    *hi = make_uint4(h[0], h[1], h[2], h[3]);
    *lo = make_uint4(l[0], l[1], l[2], l[3]);
}

#define CP_ASYNC16(dst, src) \
    asm volatile("cp.async.cg.shared.global [%0], [%1], 16;" \
        :: "r"(dst), "l"(src) : "memory")
#define CP_COMMIT() asm volatile("cp.async.commit_group;" ::: "memory")
#define CP_WAIT1()  asm volatile("cp.async.wait_group 1;" ::: "memory")

// ============================================================
// split fp32 tensor -> bf16 hi + lo
// ============================================================
__global__ __launch_bounds__(256)
void split_kernel(const float4* __restrict__ src, uint2* __restrict__ hi,
                  uint2* __restrict__ lo, int n4) {
    int i = blockIdx.x * blockDim.x + threadIdx.x;
    if (i >= n4) return;
    float4 v = src[i];
    __nv_bfloat162 h0 = __floats2bfloat162_rn(v.x, v.y);
    __nv_bfloat162 h1 = __floats2bfloat162_rn(v.z, v.w);
    __nv_bfloat162 l0 = __floats2bfloat162_rn(v.x - __bfloat162float(h0.x),
                                              v.y - __bfloat162float(h0.y));
    __nv_bfloat162 l1 = __floats2bfloat162_rn(v.z - __bfloat162float(h1.x),
                                              v.w - __bfloat162float(h1.y));
    hi[i] = make_uint2(*(uint32_t*)&h0, *(uint32_t*)&h1);
    lo[i] = make_uint2(*(uint32_t*)&l0, *(uint32_t*)&l1);
}

// ============================================================
// pre-split HMMA GEMM core: C = A @ B^T (+bias)(+relu)
// CTA 128x128, BK=32, 2-stage cp.async, 8 warps (2m x 4n), 2 CTAs/SM.
// Stride 80 B: 16B-aligned (cp.async/ldsm) and conflict-free
// (rows 0..7 -> 16B slots {0,80,32,112,64,16,96,48} mod 128).
// ============================================================
#define G3_STRIDE 80                     // bytes per smem row (32 bf16 + 16B pad)
#define G3_PART  (128 * G3_STRIDE)       // 10240
#define G3_STAGE (4 * G3_PART)           // 40960
#define G3_SMEM  (2 * G3_STAGE)          // 81920 -> 2 CTAs/SM

template<int DO_BIAS, int DO_RELU, int OUT_BF16>
__device__ __forceinline__ void gemm3_core(
    const __nv_bfloat16* __restrict__ Ah_, const __nv_bfloat16* __restrict__ Al_,
    const __nv_bfloat16* __restrict__ Bh_, const __nv_bfloat16* __restrict__ Bl_,
    const float* __restrict__ bias, float* __restrict__ C,
    __nv_bfloat16* __restrict__ Ch, __nv_bfloat16* __restrict__ Cl,
    int N, int K, char* sm, int m0, int n0) {
    const int tid = threadIdx.x;
    const int wid = tid >> 5, lane = tid & 31;
    const int wm = (wid & 1) * 64, wn = (wid >> 1) * 32;

    const __nv_bfloat16* PA0 = Ah_ + (size_t)m0 * K;
    const __nv_bfloat16* PA1 = Al_ + (size_t)m0 * K;
    const __nv_bfloat16* PA2 = Bh_ + (size_t)n0 * K;
    const __nv_bfloat16* PA3 = Bl_ + (size_t)n0 * K;

    const uint32_t sb0 = smem_u32(sm);
    const int NC = K >> 5;

    const int c_r0 = tid >> 2, c_sg = (tid & 3);

#define G3_ISSUE(cc, st) do {                                                  \
    const int kc_ = (cc) << 5;                                                 \
    const uint32_t bs_ = sb0 + (uint32_t)(st) * G3_STAGE;                      \
    _Pragma("unroll")                                                          \
    for (int it = 0; it < 2; it++) {                                           \
        const int row_ = c_r0 + it * 64;                                       \
        const uint32_t d_ = bs_ + row_ * G3_STRIDE + c_sg * 16;                \
        const size_t  o_ = (size_t)row_ * K + kc_ + c_sg * 8;                  \
        CP_ASYNC16(d_,                (const void*)(PA0 + o_));                \
        CP_ASYNC16(d_ +     G3_PART,  (const void*)(PA1 + o_));                \
        CP_ASYNC16(d_ + 2 * G3_PART,  (const void*)(PA2 + o_));                \
        CP_ASYNC16(d_ + 3 * G3_PART,  (const void*)(PA3 + o_));                \
    }                                                                          \
} while (0)

    G3_ISSUE(0, 0); CP_COMMIT();
    G3_ISSUE(1, 1); CP_COMMIT();

    float acc[4][4][4];
#pragma unroll
    for (int i = 0; i < 4; i++)
#pragma unroll
        for (int j = 0; j < 4; j++)
#pragma unroll
            for (int r = 0; r < 4; r++) acc[i][j][r] = 0.f;

    const uint32_t a_off = (uint32_t)((wm + (lane & 15)) * G3_STRIDE)
                         + ((lane >> 4) & 1) * 16;
    const uint32_t b_off = (uint32_t)((wn + (lane & 7) + ((lane >> 4) & 1) * 8) * G3_STRIDE)
                         + ((lane >> 3) & 1) * 16;

    for (int c = 0; c < NC; c++) {
        CP_WAIT1();
        __syncthreads();
        const int st = c & 1;
        const uint32_t aA = sb0 + st * G3_STAGE + a_off;
        const uint32_t aB = sb0 + st * G3_STAGE + 2 * G3_PART + b_off;
#pragma unroll
        for (int ks = 0; ks < 2; ks++) {
            uint32_t Ah[4][4], Al[4][4], Bh[4][2], Bl[4][2];
#pragma unroll
            for (int mt = 0; mt < 4; mt++)
                ldsm4(aA + mt * (16 * G3_STRIDE) + ks * 32, Ah[mt]);
#pragma unroll
            for (int mt = 0; mt < 4; mt++)
                ldsm4(aA + G3_PART + mt * (16 * G3_STRIDE) + ks * 32, Al[mt]);
#pragma unroll
            for (int bt = 0; bt < 2; bt++) {
                uint32_t r[4];
                ldsm4(aB + bt * (16 * G3_STRIDE) + ks * 32, r);
                Bh[2 * bt][0] = r[0]; Bh[2 * bt][1] = r[1];
                Bh[2 * bt + 1][0] = r[2]; Bh[2 * bt + 1][1] = r[3];
            }
#pragma unroll
            for (int bt = 0; bt < 2; bt++) {
                uint32_t r[4];
                ldsm4(aB + G3_PART + bt * (16 * G3_STRIDE) + ks * 32, r);
                Bl[2 * bt][0] = r[0]; Bl[2 * bt][1] = r[1];
                Bl[2 * bt + 1][0] = r[2]; Bl[2 * bt + 1][1] = r[3];
            }
#pragma unroll
            for (int mt = 0; mt < 4; mt++)
#pragma unroll
                for (int nt = 0; nt < 4; nt++)
                    mma16816(acc[mt][nt], Ah[mt], Bh[nt]);
#pragma unroll
            for (int mt = 0; mt < 4; mt++)
#pragma unroll
                for (int nt = 0; nt < 4; nt++)
                    mma16816(acc[mt][nt], Ah[mt], Bl[nt]);
#pragma unroll
            for (int mt = 0; mt < 4; mt++)
#pragma unroll
                for (int nt = 0; nt < 4; nt++)
                    mma16816(acc[mt][nt], Al[mt], Bh[nt]);
        }
        __syncthreads();
        if (c + 2 < NC) G3_ISSUE(c + 2, st);
        CP_COMMIT();
    }
#undef G3_ISSUE

    const int er = lane >> 2, ec = (lane & 3) * 2;
#pragma unroll
    for (int mt = 0; mt < 4; mt++) {
        const int row0 = m0 + wm + mt * 16 + er;
#pragma unroll
        for (int nt = 0; nt < 4; nt++) {
            const int col = n0 + wn + nt * 8 + ec;
            float2 bv = make_float2(0.f, 0.f);
            if (DO_BIAS) bv = *(const float2*)(bias + col);
            float2 o0, o1;
            o0.x = acc[mt][nt][0] + bv.x; o0.y = acc[mt][nt][1] + bv.y;
            o1.x = acc[mt][nt][2] + bv.x; o1.y = acc[mt][nt][3] + bv.y;
            if (DO_RELU) {
                o0.x = fmaxf(o0.x, 0.f); o0.y = fmaxf(o0.y, 0.f);
                o1.x = fmaxf(o1.x, 0.f); o1.y = fmaxf(o1.y, 0.f);
            }
            if (OUT_BF16) {
#pragma unroll
                for (int half = 0; half < 2; half++) {
                    float2 o = half ? o1 : o0;
                    const size_t off = (size_t)(row0 + half * 8) * N + col;
                    __nv_bfloat162 hb = __floats2bfloat162_rn(o.x, o.y);
                    __nv_bfloat162 lb = __floats2bfloat162_rn(o.x - __bfloat162float(hb.x),
                                                              o.y - __bfloat162float(hb.y));
                    *(uint32_t*)(Ch + off) = *(uint32_t*)&hb;
                    *(uint32_t*)(Cl + off) = *(uint32_t*)&lb;
                }
            } else {
                *(float2*)(C + (size_t)row0 * N + col)       = o0;
                *(float2*)(C + (size_t)(row0 + 8) * N + col) = o1;
            }
        }
    }
}

// QKV fused launch: grid (8, 32, 3), z selects weight/output
__global__ __launch_bounds__(256, 2)
void qkv_gemm() {
    extern __shared__ char sm[];
    const int m0 = blockIdx.y * 128, n0 = blockIdx.x * 128;
    const __nv_bfloat16 *Bh_, *Bl_;
    float* C;
    if (blockIdx.z == 0)      { Bh_ = g_wqh; Bl_ = g_wql; C = g_Yq; }
    else if (blockIdx.z == 1) { Bh_ = g_wkh; Bl_ = g_wkl; C = g_Yk; }
    else                      { Bh_ = g_wvh; Bl_ = g_wvl; C = g_Yv; }
    gemm3_core<0, 0, 0>(g_xh, g_xl, Bh_, Bl_, nullptr, C, nullptr, nullptr,
                        DM, DM, sm, m0, n0);
}

// FFN1: h1 @ w1^T + b1, relu -> mid (bf16 hi/lo)
__global__ __launch_bounds__(256, 2)
void ffn1_gemm(const float* __restrict__ b1) {
    extern __shared__ char sm[];
    gemm3_core<1, 1, 1>(g_h1h, g_h1l, g_w1h, g_w1l, b1, nullptr, g_midh, g_midl,
                        DFFN, DM, sm, blockIdx.y * 128, blockIdx.x * 128);
}

// FFN2: mid @ w2^T + b2 -> ffn (fp32)
__global__ __launch_bounds__(256, 2)
void ffn2_gemm(const float* __restrict__ b2) {
    extern __shared__ char sm[];
    gemm3_core<1, 0, 0>(g_midh, g_midl, g_w2h, g_w2l, b2, g_ffn, nullptr, nullptr,
                        DM, DFFN, sm, blockIdx.y * 128, blockIdx.x * 128);
}

// ============================================================
// emd (HMMA): emd[b,h,s,j] = sum_i Q[b,h,s,i]*relw[b,h,i,j]
// 128x128 tiles, K=64, bf16x2 split. Only band s+j>=1023 is live.
// ============================================================
#define EM_STRIDE 72
#define EM_PART (128 * EM_STRIDE * 2)   // 18432
#define EM_SCR  (4 * EM_PART)
#define EM_SMEM (4 * EM_PART + 64 * 132 * 4)   // 107520

__global__ __launch_bounds__(256, 2)
void emd_mma(const float* __restrict__ Yq, const float* __restrict__ relw,
             float* __restrict__ emd) {
    const int bh = blockIdx.z, b = bh >> 4, h = bh & 15;
    const int s0 = blockIdx.y * 128, j0 = blockIdx.x * 128;
    if (s0 + j0 < 769) return;
    extern __shared__ char sm[];
    float* scr = (float*)(sm + EM_SCR);
    const int tid = threadIdx.x;
    const int wid = tid >> 5, lane = tid & 31;
    const int wm = (wid & 1) * 64, wn = (wid >> 1) * 32;

    {
        const int lr = tid >> 1, lk = (tid & 1) * 32;
        const float* qp = Yq + (size_t)(b * SQ + s0 + lr) * DM + h * DH + lk;
        const uint32_t so = (uint32_t)(lr * EM_STRIDE + lk) * 2;
#pragma unroll
        for (int i = 0; i < 4; i++) {
            float4 v0 = *(const float4*)(qp + i * 8);
            float4 v1 = *(const float4*)(qp + i * 8 + 4);
            uint4 hh, ll;
            cvt_pack8(v0, v1, &hh, &ll);
            *(uint4*)(sm + so + i * 16)           = hh;
            *(uint4*)(sm + EM_PART + so + i * 16) = ll;
        }
    }
#pragma unroll
    for (int it = 0; it < 8; it++) {
        int f = tid + it * 256;
        int i = f >> 5, jf = (f & 31) * 4;
        float4 v = *(const float4*)(relw + ((size_t)bh * DH + i) * SQ + j0 + jf);
        *(float4*)(scr + i * 132 + jf) = v;
    }
    __syncthreads();
#pragma unroll
    for (int it = 0; it < 8; it++) {
        int u = tid + it * 256;
        int j = u & 127, i4 = (u >> 7) * 4;
        float f0 = scr[(i4 + 0) * 132 + j];
        float f1 = scr[(i4 + 1) * 132 + j];
        float f2 = scr[(i4 + 2) * 132 + j];
        float f3 = scr[(i4 + 3) * 132 + j];
        __nv_bfloat162 h01 = __floats2bfloat162_rn(f0, f1);
        __nv_bfloat162 h23 = __floats2bfloat162_rn(f2, f3);
        __nv_bfloat162 l01 = __floats2bfloat162_rn(f0 - __bfloat162float(h01.x),
                                                   f1 - __bfloat162float(h01.y));
        __nv_bfloat162 l23 = __floats2bfloat162_rn(f2 - __bfloat162float(h23.x),
                                                   f3 - __bfloat162float(h23.y));
        const uint32_t o = (uint32_t)(j * 144 + i4 * 2);
        *(uint2*)(sm + 2 * EM_PART + o) = make_uint2(*(uint32_t*)&h01, *(uint32_t*)&h23);
        *(uint2*)(sm + 3 * EM_PART + o) = make_uint2(*(uint32_t*)&l01, *(uint32_t*)&l23);
    }
    __syncthreads();

    float acc[4][4][4];
#pragma unroll
    for (int i = 0; i < 4; i++)
#pragma unroll
        for (int j = 0; j < 4; j++)
#pragma unroll
            for (int r = 0; r < 4; r++) acc[i][j][r] = 0.f;

    const uint32_t sb = smem_u32(sm);
    const uint32_t a_off = (uint32_t)((wm + (lane & 15)) * EM_STRIDE) * 2
                         + ((lane >> 4) & 1) * 16;
    const uint32_t b_off = (uint32_t)((wn + (lane & 7) + ((lane >> 4) & 1) * 8) * EM_STRIDE) * 2
                         + ((lane >> 3) & 1) * 16;

#pragma unroll
    for (int ks = 0; ks < 4; ks++) {
        uint32_t AhF[4][4], AlF[4][4], BhF[4][2], BlF[4][2];
#pragma unroll
        for (int mt = 0; mt < 4; mt++)
            ldsm4(sb + a_off + mt * 2304 + ks * 32, AhF[mt]);
#pragma unroll
        for (int mt = 0; mt < 4; mt++)
            ldsm4(sb + EM_PART + a_off + mt * 2304 + ks * 32, AlF[mt]);
#pragma unroll
        for (int bt = 0; bt < 2; bt++) {
            uint32_t r[4];
            ldsm4(sb + 2 * EM_PART + b_off + bt * 2304 + ks * 32, r);
            BhF[2 * bt][0] = r[0]; BhF[2 * bt][1] = r[1];
            BhF[2 * bt + 1][0] = r[2]; BhF[2 * bt + 1][1] = r[3];
        }
#pragma unroll
        for (int bt = 0; bt < 2; bt++) {
            uint32_t r[4];
            ldsm4(sb + 3 * EM_PART + b_off + bt * 2304 + ks * 32, r);
            BlF[2 * bt][0] = r[0]; BlF[2 * bt][1] = r[1];
            BlF[2 * bt + 1][0] = r[2]; BlF[2 * bt + 1][1] = r[3];
        }
#pragma unroll
        for (int mt = 0; mt < 4; mt++)
#pragma unroll
            for (int nt = 0; nt < 4; nt++)
                mma16816(acc[mt][nt], AhF[mt], BhF[nt]);
#pragma unroll
        for (int mt = 0; mt < 4; mt++)
#pragma unroll
            for (int nt = 0; nt < 4; nt++)
                mma16816(acc[mt][nt], AhF[mt], BlF[nt]);
#pragma unroll
        for (int mt = 0; mt < 4; mt++)
#pragma unroll
            for (int nt = 0; nt < 4; nt++)
                mma16816(acc[mt][nt], AlF[mt], BhF[nt]);
    }

    const int er = lane >> 2, ec = (lane & 3) * 2;
#pragma unroll
    for (int mt = 0; mt < 4; mt++) {
#pragma unroll
        for (int nt = 0; nt < 4; nt++) {
            const int col = j0 + wn + nt * 8 + ec;
#pragma unroll
            for (int half = 0; half < 2; half++) {
                const int sg = s0 + wm + mt * 16 + er + half * 8;
                *(float2*)(emd + (size_t)bh * SS + (size_t)sg * SQ + col) =
                    make_float2(acc[mt][nt][2 * half], acc[mt][nt][2 * half + 1]);
            }
        }
    }
}

// ============================================================
// fused attention: scores(QK^T*0.125 + skew) -> softmax over batch -> PV
// ============================================================
#define FA_B 18432
#define FA_SC_OFF 73728
#define FA_P_OFF  147456
#define FA_SMEM   221184

__global__ __launch_bounds__(256, 1)
void fused_attn(const float* __restrict__ Yq, const float* __restrict__ Yk,
                const float* __restrict__ Yv, const float* __restrict__ emd,
                float* __restrict__ out) {
    extern __shared__ char sm[];
    char* smKV = sm;
    char* smSC = sm + FA_SC_OFF;
    char* smP  = sm + FA_P_OFF;
    const int tid = threadIdx.x;
    const int wid = tid >> 5, lane = tid & 31;
    const int s0 = blockIdx.x * 64;
    const int h  = blockIdx.y;
    const int bq = wid >> 1;
    const int wm = (wid & 1) * 32;
    const int er = lane >> 2, ec = (lane & 3) * 2;

    const uint32_t sb = smem_u32(sm);
    const int lr = tid >> 1;
    const int lk = (tid & 1) * 32;

#pragma unroll
    for (int it = 0; it < 2; it++) {
        int row = lr + it * 128;
        int b = row >> 6, r = row & 63;
        const float* p = Yq + (size_t)(b * SQ + s0 + r) * DM + h * DH + lk;
        char* dst = smKV + b * FA_B + r * 144 + lk * 2;
#pragma unroll
        for (int i = 0; i < 2; i++) {
            float4 v0 = *(const float4*)(p + i * 16);
            float4 v1 = *(const float4*)(p + i * 16 + 4);
            float4 v2 = *(const float4*)(p + i * 16 + 8);
            float4 v3 = *(const float4*)(p + i * 16 + 12);
            uint4 h0, l0, h1, l1;
            cvt_pack8(v0, v1, &h0, &l0);
            cvt_pack8(v2, v3, &h1, &l1);
            *(uint4*)(dst + i * 32)              = h0;
            *(uint4*)(dst + i * 32 + 16)         = h1;
            *(uint4*)(dst + 9216 + i * 32)       = l0;
            *(uint4*)(dst + 9216 + i * 32 + 16)  = l1;
        }
    }
    __syncthreads();

    uint32_t Qh[2][4][4], Ql[2][4][4];
    {
        const uint32_t aQ = sb + (uint32_t)bq * FA_B + (wm + (lane & 15)) * 144
                          + ((lane >> 4) & 1) * 16;
#pragma unroll
        for (int mt = 0; mt < 2; mt++)
#pragma unroll
            for (int ks = 0; ks < 4; ks++) {
                ldsm4(aQ + mt * 2304 + ks * 32, Qh[mt][ks]);
                ldsm4(aQ + 9216 + mt * 2304 + ks * 32, Ql[mt][ks]);
            }
    }

    float oacc[2][8][4];
#pragma unroll
    for (int i = 0; i < 2; i++)
#pragma unroll
        for (int j = 0; j < 8; j++)
#pragma unroll
            for (int r = 0; r < 4; r++) oacc[i][j][r] = 0.f;

    const uint32_t kvB = sb + (uint32_t)bq * FA_B
                       + ((lane & 7) + ((lane >> 4) & 1) * 8) * 144
                       + ((lane >> 3) & 1) * 16;
    const uint32_t aP = sb + FA_P_OFF + (uint32_t)bq * FA_B
                      + (wm + (lane & 15)) * 144 + ((lane >> 4) & 1) * 16;
    const size_t ebase = (size_t)(bq * NH + h) * SS;

    for (int t0 = 0; t0 < SQ; t0 += 64) {
        __syncthreads();

#pragma unroll
        for (int it = 0; it < 2; it++) {
            int row = lr + it * 128;
            int b = row >> 6, r = row & 63;
            const float* p = Yk + (size_t)(b * SQ + t0 + r) * DM + h * DH + lk;
            char* dst = smKV + b * FA_B + r * 144 + lk * 2;
#pragma unroll
            for (int i = 0; i < 2; i++) {
                float4 v0 = *(const float4*)(p + i * 16);
                float4 v1 = *(const float4*)(p + i * 16 + 4);
                float4 v2 = *(const float4*)(p + i * 16 + 8);
                float4 v3 = *(const float4*)(p + i * 16 + 12);
                uint4 h0, l0, h1, l1;
                cvt_pack8(v0, v1, &h0, &l0);
                cvt_pack8(v2, v3, &h1, &l1);
                *(uint4*)(dst + i * 32)              = h0;
                *(uint4*)(dst + i * 32 + 16)         = h1;
                *(uint4*)(dst + 9216 + i * 32)       = l0;
                *(uint4*)(dst + 9216 + i * 32 + 16)  = l1;
            }
        }
        __syncthreads();

        float qk[2][8][4];
#pragma unroll
        for (int i = 0; i < 2; i++)
#pragma unroll
            for (int j = 0; j < 8; j++)
#pragma unroll
                for (int r = 0; r < 4; r++) qk[i][j][r] = 0.f;
#pragma unroll
        for (int ks = 0; ks < 4; ks++) {
            uint32_t Bh[8][2], Bl[8][2];
#pragma unroll
            for (int bt = 0; bt < 4; bt++) {
                uint32_t r[4];
                ldsm4(kvB + bt * 2304 + ks * 32, r);
                Bh[2 * bt][0] = r[0]; Bh[2 * bt][1] = r[1];
                Bh[2 * bt + 1][0] = r[2]; Bh[2 * bt + 1][1] = r[3];
            }
#pragma unroll
            for (int bt = 0; bt < 4; bt++) {
                uint32_t r[4];
                ldsm4(kvB + 9216 + bt * 2304 + ks * 32, r);
                Bl[2 * bt][0] = r[0]; Bl[2 * bt][1] = r[1];
                Bl[2 * bt + 1][0] = r[2]; Bl[2 * bt + 1][1] = r[3];
            }
#pragma unroll
            for (int mt = 0; mt < 2; mt++)
#pragma unroll
                for (int nt = 0; nt < 8; nt++)
                    mma16816(qk[mt][nt], Qh[mt][ks], Bh[nt]);
#pragma unroll
            for (int mt = 0; mt < 2; mt++)
#pragma unroll
                for (int nt = 0; nt < 8; nt++)
                    mma16816(qk[mt][nt], Qh[mt][ks], Bl[nt]);
#pragma unroll
            for (int mt = 0; mt < 2; mt++)
#pragma unroll
                for (int nt = 0; nt < 8; nt++)
                    mma16816(qk[mt][nt], Ql[mt][ks], Bh[nt]);
        }

#pragma unroll
        for (int mt = 0; mt < 2; mt++) {
#pragma unroll
            for (int nt = 0; nt < 8; nt++) {
                const int tg = nt * 8 + ec;
                const int tgl = t0 + tg;
#pragma unroll
                for (int half = 0; half < 2; half++) {
                    const int sg = wm + mt * 16 + er + half * 8;
                    const int sgl = s0 + sg;
                    float v0 = 0.125f * qk[mt][nt][2 * half];
                    float v1 = 0.125f * qk[mt][nt][2 * half + 1];
                    if (tgl <= sgl)
                        v0 += emd[ebase + (size_t)sgl * SQ + 1023 + tgl - sgl];
                    if (tgl + 1 <= sgl)
                        v1 += emd[ebase + (size_t)sgl * SQ + 1024 + tgl - sgl];
                    *(float2*)(smSC + bq * FA_B + sg * 288 + tg * 4) = make_float2(v0, v1);
                }
            }
        }
        __syncthreads();

#pragma unroll
        for (int i = 0; i < 8; i++) {
            const int e = tid + i * 256;
            const int s = e >> 5, t2 = (e & 31) * 2;
            float2 v[4];
#pragma unroll
            for (int b = 0; b < 4; b++)
                v[b] = *(const float2*)(smSC + b * FA_B + s * 288 + t2 * 4);
            float m0 = fmaxf(fmaxf(v[0].x, v[1].x), fmaxf(v[2].x, v[3].x));
            float m1 = fmaxf(fmaxf(v[0].y, v[1].y), fmaxf(v[2].y, v[3].y));
            float e0[4], e1[4];
            float sum0 = 0.f, sum1 = 0.f;
#pragma unroll
            for (int b = 0; b < 4; b++) {
                e0[b] = __expf(v[b].x - m0); sum0 += e0[b];
                e1[b] = __expf(v[b].y - m1); sum1 += e1[b];
            }
            const float i0 = 1.f / sum0, i1 = 1.f / sum1;
#pragma unroll
            for (int b = 0; b < 4; b++) {
                float p0 = e0[b] * i0, p1 = e1[b] * i1;
                __nv_bfloat162 hb = __floats2bfloat162_rn(p0, p1);
                float r0 = p0 - __bfloat162float(hb.x);
                float r1 = p1 - __bfloat162float(hb.y);
                __nv_bfloat162 lb = __floats2bfloat162_rn(r0, r1);
                *(uint32_t*)(smP + b * FA_B + s * 144 + t2 * 2)        = *(uint32_t*)&hb;
                *(uint32_t*)(smP + b * FA_B + 9216 + s * 144 + t2 * 2) = *(uint32_t*)&lb;
            }
        }
#pragma unroll
        for (int it = 0; it < 4; it++) {
            const int f = tid + it * 256;
            const int d = f & 63;
            const int t4 = (f >> 6) * 4;
#pragma unroll
            for (int b = 0; b < 4; b++) {
                const float* vp = Yv + (size_t)(b * SQ + t0 + t4) * DM + h * DH + d;
                float v0 = vp[0];
                float v1 = vp[DM];
                float v2 = vp[2 * DM];
                float v3 = vp[3 * DM];
                __nv_bfloat162 h01 = __floats2bfloat162_rn(v0, v1);
                __nv_bfloat162 h23 = __floats2bfloat162_rn(v2, v3);
                __nv_bfloat162 l01 = __floats2bfloat162_rn(v0 - __bfloat162float(h01.x),
                                                           v1 - __bfloat162float(h01.y));
                __nv_bfloat162 l23 = __floats2bfloat162_rn(v2 - __bfloat162float(h23.x),
                                                           v3 - __bfloat162float(h23.y));
                char* vb = smKV + b * FA_B;
                const uint32_t vo = (uint32_t)(d * 144 + t4 * 2);
                *(uint2*)(vb + vo)        = make_uint2(*(uint32_t*)&h01, *(uint32_t*)&h23);
                *(uint2*)(vb + 9216 + vo) = make_uint2(*(uint32_t*)&l01, *(uint32_t*)&l23);
            }
        }
        __syncthreads();

#pragma unroll
        for (int ks = 0; ks < 4; ks++) {
            uint32_t Ph[2][4], Pl[2][4], Vh[8][2], Vl[8][2];
#pragma unroll
            for (int mt = 0; mt < 2; mt++) {
                ldsm4(aP + mt * 2304 + ks * 32, Ph[mt]);
                ldsm4(aP + 9216 + mt * 2304 + ks * 32, Pl[mt]);
            }
#pragma unroll
            for (int bt = 0; bt < 4; bt++) {
                uint32_t r[4];
                ldsm4(kvB + bt * 2304 + ks * 32, r);
                Vh[2 * bt][0] = r[0]; Vh[2 * bt][1] = r[1];
                Vh[2 * bt + 1][0] = r[2]; Vh[2 * bt + 1][1] = r[3];
            }
#pragma unroll
            for (int bt = 0; bt < 4; bt++) {
                uint32_t r[4];
                ldsm4(kvB + 9216 + bt * 2304 + ks * 32, r);
                Vl[2 * bt][0] = r[0]; Vl[2 * bt][1] = r[1];
                Vl[2 * bt + 1][0] = r[2]; Vl[2 * bt + 1][1] = r[3];
            }
#pragma unroll
            for (int mt = 0; mt < 2; mt++)
#pragma unroll
                for (int nt = 0; nt < 8; nt++)
                    mma16816(oacc[mt][nt], Ph[mt], Vh[nt]);
#pragma unroll
            for (int mt = 0; mt < 2; mt++)
#pragma unroll
                for (int nt = 0; nt < 8; nt++)
                    mma16816(oacc[mt][nt], Ph[mt], Vl[nt]);
#pragma unroll
            for (int mt = 0; mt < 2; mt++)
#pragma unroll
                for (int nt = 0; nt < 8; nt++)
                    mma16816(oacc[mt][nt], Pl[mt], Vh[nt]);
        }
    }

#pragma unroll
    for (int mt = 0; mt < 2; mt++) {
        const int row = s0 + wm + mt * 16 + er;
        float* op = out + ((size_t)(bq * NH + h) * SQ + row) * DH;
#pragma unroll
        for (int nt = 0; nt < 8; nt++) {
            const int col = nt * 8 + ec;
            *(float2*)(op + col)          = make_float2(oacc[mt][nt][0], oacc[mt][nt][1]);
            *(float2*)(op + 8 * DH + col) = make_float2(oacc[mt][nt][2], oacc[mt][nt][3]);
        }
    }
}

// ============================================================
// residual + LayerNorm (optionally emitting bf16 hi/lo split)
// ============================================================
__device__ __forceinline__ float block_sum256(float v, float* red) {
#pragma unroll
    for (int o = 16; o > 0; o >>= 1) v += __shfl_xor_sync(0xffffffffu, v, o);
    int t = threadIdx.x;
    if ((t & 31) == 0) red[t >> 5] = v;
    __syncthreads();
    if (t == 0) {
        float s = 0.f;
#pragma unroll
        for (int i = 0; i < 8; i++) s += red[i];
        red[0] = s;
    }
    __syncthreads();
    float res = red[0];
    __syncthreads();
    return res;
}

template<int SPLIT>
__global__ __launch_bounds__(256)
void add_ln_kernel(const float* __restrict__ xa, const float* __restrict__ xb,
                   const float* __restrict__ g, const float* __restrict__ bb,
                   float* __restrict__ out,
                   __nv_bfloat16* __restrict__ oh, __nv_bfloat16* __restrict__ ol) {
    const int row = blockIdx.x;
    const float* pa = xa + (size_t)row * DM;
    const float* pb = xb + (size_t)row * DM;
    __shared__ float red[8];
    const int t = threadIdx.x;

    float loc[4];
    float s = 0.f;
#pragma unroll
    for (int u = 0; u < 4; u++) {
        int i = t + u * 256;
        float v = pa[i] + pb[i];
        loc[u] = v;
        s += v;
    }
    float mean = block_sum256(s, red) * (1.f / 1024.f);

    float vs = 0.f;
#pragma unroll
    for (int u = 0; u < 4; u++) {
        float d = loc[u] - mean;
        vs += d * d;
    }
    float var = block_sum256(vs, red) * (1.f / 1024.f);
    float inv = rsqrtf(var + EPSV);

#pragma unroll
    for (int u = 0; u < 4; u++) {
        int i = t + u * 256;
        float o = (loc[u] - mean) * inv * g[i] + bb[i];
        out[(size_t)row * DM + i] = o;
        if (SPLIT) {
            __nv_bfloat16 hb = __float2bfloat16_rn(o);
            __nv_bfloat16 lb = __float2bfloat16_rn(o - __bfloat162float(hb));
            oh[(size_t)row * DM + i] = hb;
            ol[(size_t)row * DM + i] = lb;
        }
    }
}

// ============================================================
extern "C" void kernel_launch(void* const* d_in, const int* in_sizes, int n_in,
                              void* d_out, int out_size) {
    const float* x    = (const float*)d_in[0];
    const float* wq   = (const float*)d_in[1];
    const float* wk   = (const float*)d_in[2];
    const float* wv   = (const float*)d_in[3];
    const float* relw = (const float*)d_in[4];
    const float* ln1g = (const float*)d_in[5];
    const float* ln1b = (const float*)d_in[6];
    const float* ln2g = (const float*)d_in[7];
    const float* ln2b = (const float*)d_in[8];
    const float* w1   = (const float*)d_in[9];
    const float* b1   = (const float*)d_in[10];
    const float* w2   = (const float*)d_in[11];
    const float* b2   = (const float*)d_in[12];
    float* out = (float*)d_out;

    float *Yq, *Yk, *Yv, *emd, *att, *h1;
    __nv_bfloat16 *xh, *xl, *wqh, *wql, *wkh, *wkl, *wvh, *wvl;
    __nv_bfloat16 *w1h, *w1l, *w2h, *w2l, *h1h, *h1l;
    float* ffn;
    cudaGetSymbolAddress((void**)&Yq,  g_Yq);
    cudaGetSymbolAddress((void**)&Yk,  g_Yk);
    cudaGetSymbolAddress((void**)&Yv,  g_Yv);
    cudaGetSymbolAddress((void**)&emd, g_emd);
    cudaGetSymbolAddress((void**)&att, g_att);
    cudaGetSymbolAddress((void**)&h1,  g_h1);
    cudaGetSymbolAddress((void**)&ffn, g_ffn);
    cudaGetSymbolAddress((void**)&xh,  g_xh);   cudaGetSymbolAddress((void**)&xl,  g_xl);
    cudaGetSymbolAddress((void**)&wqh, g_wqh);  cudaGetSymbolAddress((void**)&wql, g_wql);
    cudaGetSymbolAddress((void**)&wkh, g_wkh);  cudaGetSymbolAddress((void**)&wkl, g_wkl);
    cudaGetSymbolAddress((void**)&wvh, g_wvh);  cudaGetSymbolAddress((void**)&wvl, g_wvl);
    cudaGetSymbolAddress((void**)&w1h, g_w1h);  cudaGetSymbolAddress((void**)&w1l, g_w1l);
    cudaGetSymbolAddress((void**)&w2h, g_w2h);  cudaGetSymbolAddress((void**)&w2l, g_w2l);
    cudaGetSymbolAddress((void**)&h1h, g_h1h);  cudaGetSymbolAddress((void**)&h1l, g_h1l);

    cudaFuncSetAttribute(qkv_gemm,  cudaFuncAttributeMaxDynamicSharedMemorySize, G3_SMEM);
    cudaFuncSetAttribute(ffn1_gemm, cudaFuncAttributeMaxDynamicSharedMemorySize, G3_SMEM);
    cudaFuncSetAttribute(ffn2_gemm, cudaFuncAttributeMaxDynamicSharedMemorySize, G3_SMEM);
    cudaFuncSetAttribute(emd_mma, cudaFuncAttributeMaxDynamicSharedMemorySize, EM_SMEM);
    cudaFuncSetAttribute(fused_attn, cudaFuncAttributeMaxDynamicSharedMemorySize, FA_SMEM);

    // ---- split pre-pass: x + all weights ----
    split_kernel<<<(NROW * DM / 4 + 255) / 256, 256>>>((const float4*)x, (uint2*)xh, (uint2*)xl, NROW * DM / 4);
    split_kernel<<<(DM * DM / 4 + 255) / 256, 256>>>((const float4*)wq, (uint2*)wqh, (uint2*)wql, DM * DM / 4);
    split_kernel<<<(DM * DM / 4 + 255) / 256, 256>>>((const float4*)wk, (uint2*)wkh, (uint2*)wkl, DM * DM / 4);
    split_kernel<<<(DM * DM / 4 + 255) / 256, 256>>>((const float4*)wv, (uint2*)wvh, (uint2*)wvl, DM * DM / 4);
    split_kernel<<<(DFFN * DM / 4 + 255) / 256, 256>>>((const float4*)w1, (uint2*)w1h, (uint2*)w1l, DFFN * DM / 4);
    split_kernel<<<(DM * DFFN / 4 + 255) / 256, 256>>>((const float4*)w2, (uint2*)w2h, (uint2*)w2l, DM * DFFN / 4);

    // ---- QKV projections (one fused launch, 2 CTAs/SM) ----
    qkv_gemm<<<dim3(DM / 128, NROW / 128, 3), 256, G3_SMEM>>>();

    // ---- relative-position logits (live band only) ----
    emd_mma<<<dim3(8, 8, 64), 256, EM_SMEM>>>(Yq, relw, emd);

    // ---- fused scores + skew + batch-softmax + PV ----
    fused_attn<<<dim3(16, 16), 256, FA_SMEM>>>(Yq, Yk, Yv, emd, att);

    // ---- residual + LN1 (emit fp32 + bf16 split) ----
    add_ln_kernel<1><<<NROW, 256>>>(x, att, ln1g, ln1b, h1, h1h, h1l);

    // ---- FFN1: h1 @ w1^T + b1, relu -> mid (bf16 hi/lo) ----
    ffn1_gemm<<<dim3(DFFN / 128, NROW / 128), 256, G3_SMEM>>>(b1);

    // ---- FFN2: mid @ w2^T + b2 -> ffn (fp32) ----
    ffn2_gemm<<<dim3(DM / 128, NROW / 128), 256, G3_SMEM>>>(b2);

    // ---- residual + LN2 -> output ----
    add_ln_kernel<0><<<NROW, 256>>>(h1, ffn, ln2g, ln2b, out, nullptr, nullptr);

    (void)in_sizes; (void)n_in; (void)out_size;
}